// round 9
// baseline (speedup 1.0000x reference)
#include <cuda_runtime.h>
#include <cuda_bf16.h>
#include <cstdint>
#include <math.h>

#define Tt 128
#define Bb 64
#define Ff 512
#define Hh 1024
#define NG 4096
#define TBm 8192
#define OUTF 513
#define NOP 640           // padded output cols
#define NBLK 128

static __device__ float d_Bcat[NG];
static __device__ float d_G[(size_t)TBm*NG];
static __device__ __nv_bfloat16 d_Wbhi[(size_t)Ff*NG];
static __device__ __nv_bfloat16 d_Wblo[(size_t)Ff*NG];
static __device__ __nv_bfloat16 d_Xhi[(size_t)TBm*Ff];
static __device__ __nv_bfloat16 d_Xlo[(size_t)TBm*Ff];
static __device__ __nv_bfloat16 d_Ubhi[(size_t)Hh*NG];
static __device__ __nv_bfloat16 d_Ublo[(size_t)Hh*NG];
static __device__ __nv_bfloat16 d_Hallhi[(size_t)TBm*Hh];
static __device__ __nv_bfloat16 d_Halllo[(size_t)TBm*Hh];
static __device__ __nv_bfloat16 d_WoP_hi[(size_t)Hh*NOP];
static __device__ __nv_bfloat16 d_WoP_lo[(size_t)Hh*NOP];
static __device__ unsigned g_bar;

__constant__ int   c_CM[16] = {0,1,2,3, 1,0,3,2, 2,3,0,1, 3,2,1,0};
__constant__ float c_SG[16] = {1,1,1,1, -1,1,1,-1, -1,-1,1,1, -1,1,-1,1};

// ---- PTX helpers (sm_80-baseline, valid on sm_103) ----
__device__ __forceinline__ uint32_t smem_u32(const void* p){
    uint32_t a; asm("{ .reg .u64 t; cvta.to.shared.u64 t, %1; cvt.u32.u64 %0, t; }":"=r"(a):"l"(p)); return a;
}
#define LDSM4(r,a) asm volatile("ldmatrix.sync.aligned.m8n8.x4.shared.b16 {%0,%1,%2,%3}, [%4];" \
    :"=r"((r)[0]),"=r"((r)[1]),"=r"((r)[2]),"=r"((r)[3]):"r"(a))
#define LDSM4T(r,a) asm volatile("ldmatrix.sync.aligned.m8n8.x4.trans.shared.b16 {%0,%1,%2,%3}, [%4];" \
    :"=r"((r)[0]),"=r"((r)[1]),"=r"((r)[2]),"=r"((r)[3]):"r"(a))
#define MMA16816(c,a,b0,b1) asm volatile( \
    "mma.sync.aligned.m16n8k16.row.col.f32.bf16.bf16.f32 {%0,%1,%2,%3},{%4,%5,%6,%7},{%8,%9},{%0,%1,%2,%3};" \
    :"+f"((c)[0]),"+f"((c)[1]),"+f"((c)[2]),"+f"((c)[3]) \
    :"r"((a)[0]),"r"((a)[1]),"r"((a)[2]),"r"((a)[3]),"r"(b0),"r"(b1))
#define CPA16(dst,src) asm volatile("cp.async.cg.shared.global [%0], [%1], 16;"::"r"(dst),"l"(src))
#define CPA_COMMIT()   asm volatile("cp.async.commit_group;":::"memory")
#define CPA_WAIT1()    asm volatile("cp.async.wait_group 1;":::"memory")
#define CPA_WAIT0()    asm volatile("cp.async.wait_group 0;":::"memory")

// ---- builds (gate-interleaved cols: col = 4h + g) ----
__global__ void k_build_wbf(const float* __restrict__ wf, const float* __restrict__ wi,
                            const float* __restrict__ wo, const float* __restrict__ wc){
    int idx = blockIdx.x*blockDim.x + threadIdx.x;
    if (idx >= Ff*NG) return;
    int k = idx >> 12, c = idx & (NG-1);
    int g = c & 3, hh = c >> 2;
    int cb = hh>>8, bbp = hh&255, rb = k>>7, aa = k&127;
    const float* w = (g==0)?wf:(g==1)?wi:(g==2)?wo:wc;
    int m = rb*4+cb;
    float v = c_SG[m]*w[((size_t)c_CM[m]*128+aa)*256+bbp];
    __nv_bfloat16 hi = __float2bfloat16_rn(v);
    d_Wbhi[idx] = hi;
    d_Wblo[idx] = __float2bfloat16_rn(v - __bfloat162float(hi));
}
__global__ void k_split_x(const float* __restrict__ x){
    int idx = blockIdx.x*blockDim.x + threadIdx.x;
    if (idx >= TBm*Ff) return;
    float v = x[idx];
    __nv_bfloat16 hi = __float2bfloat16_rn(v);
    d_Xhi[idx] = hi;
    d_Xlo[idx] = __float2bfloat16_rn(v - __bfloat162float(hi));
}
__global__ void k_build_u(const float* __restrict__ uf, const float* __restrict__ ui,
                          const float* __restrict__ uo, const float* __restrict__ uc){
    int idx = blockIdx.x*blockDim.x + threadIdx.x;
    if (idx >= Hh*NG) return;
    int k = idx >> 12, c = idx & (NG-1);
    int g = c & 3, hh = c >> 2;
    int cb = hh>>8, bbp = hh&255, rb = k>>8, aa = k&255;
    const float* u = (g==0)?uf:(g==1)?ui:(g==2)?uo:uc;
    int m = rb*4+cb;
    float v = c_SG[m]*u[((size_t)c_CM[m]*256+aa)*256+bbp];
    __nv_bfloat16 hi = __float2bfloat16_rn(v);
    d_Ubhi[idx] = hi;
    d_Ublo[idx] = __float2bfloat16_rn(v - __bfloat162float(hi));
}
__global__ void k_build_wout(const float* __restrict__ Wo){
    int idx = blockIdx.x*blockDim.x + threadIdx.x;
    if (idx >= Hh*NOP) return;
    int k = idx / NOP, n = idx % NOP;
    float v = (n < OUTF) ? Wo[(size_t)k*OUTF + n] : 0.f;
    __nv_bfloat16 hi = __float2bfloat16_rn(v);
    d_WoP_hi[idx] = hi;
    d_WoP_lo[idx] = __float2bfloat16_rn(v - __bfloat162float(hi));
}
__global__ void k_build_misc(const float* __restrict__ bf, const float* __restrict__ bi,
                             const float* __restrict__ bo, const float* __restrict__ bc){
    int idx = blockIdx.x*blockDim.x + threadIdx.x;
    if (idx == 0) g_bar = 0u;
    if (idx < NG){
        int g = idx & 3, hh = idx >> 2;
        const float* b = (g==0)?bf:(g==1)?bi:(g==2)?bo:bc;
        d_Bcat[idx] = b[hh];
    }
}

// ---- HMMA GEMM tiles: 128x128 block, K-chunk 64, 8 warps (4m x 2n) ----
#define IA_STR 144
#define IB_STR 272
#define IA_SZ  (128*IA_STR)
#define IB_SZ  (64*IB_STR)
#define IBUF   (2*IA_SZ + 2*IB_SZ)
#define ISMEM  (2*IBUF)

__device__ __forceinline__ void tile_load(char* buf,
        const __nv_bfloat16* Ahi, const __nv_bfloat16* Alo, int astride,
        const __nv_bfloat16* Bhi, const __nv_bfloat16* Blo, int bstride,
        int row0, int col0, int kc, int tid){
    const __nv_bfloat16* Ac[2] = {Ahi, Alo};
    const __nv_bfloat16* Bc[2] = {Bhi, Blo};
#pragma unroll
    for (int j = 0; j < 8; j++){
        int i = tid + j*256;
        int comp = i >> 10, rem = i & 1023, r = rem >> 3, s = rem & 7;
        const char* src = (const char*)(Ac[comp] + (size_t)(row0 + r)*astride + kc*64 + s*8);
        CPA16(smem_u32(buf + comp*IA_SZ + r*IA_STR + s*16), src);
    }
    char* bbuf = buf + 2*IA_SZ;
#pragma unroll
    for (int j = 0; j < 8; j++){
        int i = tid + j*256;
        int comp = i >> 10, rem = i & 1023, r = rem >> 4, s = rem & 15;
        const char* src = (const char*)(Bc[comp] + (size_t)(kc*64 + r)*bstride + col0 + s*8);
        CPA16(smem_u32(bbuf + comp*IB_SZ + r*IB_STR + s*16), src);
    }
    CPA_COMMIT();
}

__device__ __forceinline__ void tile_mma(char* abuf, char* bbuf, int wm, int wn, int lane,
                                         float acc[2][8][4]){
#pragma unroll
    for (int ks = 0; ks < 4; ks++){
        uint32_t ah[2][4], al[2][4], bh[4][4], bl[4][4];
#pragma unroll
        for (int mi = 0; mi < 2; mi++){
            uint32_t aoff = (wm*32 + mi*16 + (lane&15))*IA_STR + ks*32 + (lane>>4)*16;
            LDSM4(ah[mi], smem_u32(abuf + aoff));
            LDSM4(al[mi], smem_u32(abuf + IA_SZ + aoff));
        }
#pragma unroll
        for (int ni = 0; ni < 4; ni++){
            uint32_t boff = (ks*16 + (lane&15))*IB_STR + wn*128 + ni*32 + (lane>>4)*16;
            LDSM4T(bh[ni], smem_u32(bbuf + boff));
            LDSM4T(bl[ni], smem_u32(bbuf + IB_SZ + boff));
        }
#pragma unroll
        for (int mi = 0; mi < 2; mi++)
#pragma unroll
            for (int ni = 0; ni < 4; ni++){
                MMA16816(acc[mi][2*ni],   ah[mi], bh[ni][0], bh[ni][1]);
                MMA16816(acc[mi][2*ni],   ah[mi], bl[ni][0], bl[ni][1]);
                MMA16816(acc[mi][2*ni],   al[mi], bh[ni][0], bh[ni][1]);
                MMA16816(acc[mi][2*ni+1], ah[mi], bh[ni][2], bh[ni][3]);
                MMA16816(acc[mi][2*ni+1], ah[mi], bl[ni][2], bl[ni][3]);
                MMA16816(acc[mi][2*ni+1], al[mi], bh[ni][2], bh[ni][3]);
            }
    }
}

__global__ __launch_bounds__(256,1) void k_gemm_in_mma(){
    extern __shared__ char sm[];
    const int tid = threadIdx.x, lane = tid&31, w = tid>>5;
    const int wm = w&3, wn = w>>2;
    const int col0 = blockIdx.x*128, row0 = blockIdx.y*128;
    float acc[2][8][4];
#pragma unroll
    for (int mi=0;mi<2;mi++)
#pragma unroll
        for (int nj=0;nj<8;nj++)
#pragma unroll
            for (int q=0;q<4;q++) acc[mi][nj][q]=0.f;

    tile_load(sm, d_Xhi, d_Xlo, Ff, d_Wbhi, d_Wblo, NG, row0, col0, 0, tid);
    for (int kc = 0; kc < 8; kc++){
        if (kc < 7) tile_load(sm + ((kc+1)&1)*IBUF, d_Xhi, d_Xlo, Ff, d_Wbhi, d_Wblo, NG,
                              row0, col0, kc+1, tid);
        if (kc < 7) CPA_WAIT1(); else CPA_WAIT0();
        __syncthreads();
        char* abuf = sm + (kc&1)*IBUF;
        tile_mma(abuf, abuf + 2*IA_SZ, wm, wn, lane, acc);
        __syncthreads();
    }
#pragma unroll
    for (int mi = 0; mi < 2; mi++){
        int r = wm*32 + mi*16 + (lane>>2);
#pragma unroll
        for (int nj = 0; nj < 8; nj++){
            int c = col0 + wn*64 + nj*8 + (lane&3)*2;
            float2 bc = *(const float2*)&d_Bcat[c];
            size_t g0 = (size_t)(row0 + r)*NG + c;
            *(float2*)&d_G[g0] = make_float2(acc[mi][nj][0] + bc.x, acc[mi][nj][1] + bc.y);
            *(float2*)&d_G[g0 + 8*NG] = make_float2(acc[mi][nj][2] + bc.x, acc[mi][nj][3] + bc.y);
        }
    }
}

// ---- HMMA output GEMM: Out = Hall @ WoP + bias (N padded to 640) ----
// NOTE: OUTF=513 is odd -> Out rows are only 4B-aligned; epilogue uses SCALAR stores.
__global__ __launch_bounds__(256,1) void k_gemm_out_mma(const float* __restrict__ bout,
                                                        float* __restrict__ Out){
    extern __shared__ char sm[];
    const int tid = threadIdx.x, lane = tid&31, w = tid>>5;
    const int wm = w&3, wn = w>>2;
    const int col0 = blockIdx.x*128, row0 = blockIdx.y*128;
    float acc[2][8][4];
#pragma unroll
    for (int mi=0;mi<2;mi++)
#pragma unroll
        for (int nj=0;nj<8;nj++)
#pragma unroll
            for (int q=0;q<4;q++) acc[mi][nj][q]=0.f;

    tile_load(sm, d_Hallhi, d_Halllo, Hh, d_WoP_hi, d_WoP_lo, NOP, row0, col0, 0, tid);
    for (int kc = 0; kc < 16; kc++){
        if (kc < 15) tile_load(sm + ((kc+1)&1)*IBUF, d_Hallhi, d_Halllo, Hh, d_WoP_hi, d_WoP_lo, NOP,
                               row0, col0, kc+1, tid);
        if (kc < 15) CPA_WAIT1(); else CPA_WAIT0();
        __syncthreads();
        char* abuf = sm + (kc&1)*IBUF;
        tile_mma(abuf, abuf + 2*IA_SZ, wm, wn, lane, acc);
        __syncthreads();
    }
#pragma unroll
    for (int mi = 0; mi < 2; mi++){
        int r = wm*32 + mi*16 + (lane>>2);
#pragma unroll
        for (int nj = 0; nj < 8; nj++){
            int c = col0 + wn*64 + nj*8 + (lane&3)*2;
#pragma unroll
            for (int e = 0; e < 2; e++){
                int cc = c + e;
                if (cc < OUTF){
                    float bc = bout[cc];
                    size_t o0 = (size_t)(row0 + r)*OUTF + cc;
                    Out[o0]            = acc[mi][nj][e]     + bc;
                    Out[o0 + 8*OUTF]   = acc[mi][nj][e + 2] + bc;
                }
            }
        }
    }
}

// ---- persistent HMMA recurrence (cp.async staging) ----
#define OFF_ULO  81920
#define OFF_HS   163840
#define HS_BUF   18432
#define HS_COMP  9216
#define OFF_EX   200704
#define RSMEM    (200704 + 8448)

__device__ __forceinline__ void grid_bar(unsigned target){
    __syncthreads();
    if (threadIdx.x == 0){
        __threadfence();
        atomicAdd(&g_bar, 1u);
        while (*(volatile unsigned*)&g_bar < target) { }
        __threadfence();
    }
    __syncthreads();
}

__global__ __launch_bounds__(256,1) void k_recur_mma(){
    extern __shared__ char sm[];
    const int tid = threadIdx.x, lane = tid&31, w = tid>>5;
    const int blk = blockIdx.x;
    const int c0 = blk*32, u0 = blk*8;
    const int wm = w&3, wn = w>>2;
    char* UHI = sm;
    char* ULO = sm + OFF_ULO;
    char* HSB = sm + OFF_HS;
    float* exch = (float*)(sm + OFF_EX);

    for (int i = tid; i < 1024*4; i += 256){
        int k = i>>2, s = i&3;
        *(uint4*)(UHI + k*80 + s*16) =
            *(const uint4*)((const char*)(d_Ubhi + (size_t)k*NG + c0) + s*16);
        *(uint4*)(ULO + k*80 + s*16) =
            *(const uint4*)((const char*)(d_Ublo + (size_t)k*NG + c0) + s*16);
    }

    float cst[2] = {0.f, 0.f};
    const int pb = tid>>2;
    const int pu = (tid&3)*2;

    for (int t = 0; t < Tt; t++){
        if (t > 0){
            const char* hhi = (const char*)(d_Hallhi + ((size_t)(t-1)*Bb << 10));
            const char* hlo = (const char*)(d_Halllo + ((size_t)(t-1)*Bb << 10));
#pragma unroll
            for (int j = 0; j < 4; j++){
                int i = tid + j*256; int comp = i>>9, r = (i>>3)&63, s = i&7;
                CPA16(smem_u32(HSB + comp*HS_COMP + r*144 + s*16),
                      (comp?hlo:hhi) + r*2048 + s*16);
            }
            CPA_COMMIT(); CPA_WAIT0();
            __syncthreads();

            float acc[6][4];
#pragma unroll
            for (int p=0;p<6;p++)
#pragma unroll
                for (int q=0;q<4;q++) acc[p][q]=0.f;

            for (int kc = 0; kc < 16; kc++){
                if (kc < 15){
                    char* nb = HSB + ((kc+1)&1)*HS_BUF;
#pragma unroll
                    for (int j = 0; j < 4; j++){
                        int i = tid + j*256; int comp = i>>9, r = (i>>3)&63, s = i&7;
                        CPA16(smem_u32(nb + comp*HS_COMP + r*144 + s*16),
                              (comp?hlo:hhi) + r*2048 + (kc+1)*128 + s*16);
                    }
                    CPA_COMMIT();
                }
                char* hs = HSB + (kc&1)*HS_BUF;
#pragma unroll
                for (int ks = 0; ks < 4; ks++){
                    uint32_t ah[4], al[4], bh[4], bl[4];
                    uint32_t aoff = (wm*16 + (lane&15))*144 + ks*32 + (lane>>4)*16;
                    LDSM4(ah, smem_u32(hs + aoff));
                    LDSM4(al, smem_u32(hs + HS_COMP + aoff));
                    uint32_t brow = kc*64 + ks*16 + (lane&15);
                    uint32_t boff = brow*80 + wn*32 + (lane>>4)*16;
                    LDSM4T(bh, smem_u32(UHI + boff));
                    LDSM4T(bl, smem_u32(ULO + boff));
                    MMA16816(acc[0], ah, bh[0], bh[1]);
                    MMA16816(acc[1], ah, bl[0], bl[1]);
                    MMA16816(acc[2], al, bh[0], bh[1]);
                    MMA16816(acc[3], ah, bh[2], bh[3]);
                    MMA16816(acc[4], ah, bl[2], bl[3]);
                    MMA16816(acc[5], al, bh[2], bh[3]);
                }
                if (kc < 15){
                    CPA_WAIT0();
                    __syncthreads();
                }
            }
            {
                int r0 = wm*16 + (lane>>2);
                int cb = wn*16 + (lane&3)*2;
                float s0[4], s1[4];
#pragma unroll
                for (int q=0;q<4;q++){
                    s0[q] = acc[0][q] + acc[1][q] + acc[2][q];
                    s1[q] = acc[3][q] + acc[4][q] + acc[5][q];
                }
                exch[r0*33 + cb]       = s0[0];
                exch[r0*33 + cb + 1]   = s0[1];
                exch[(r0+8)*33 + cb]   = s0[2];
                exch[(r0+8)*33 + cb+1] = s0[3];
                exch[r0*33 + cb + 8]       = s1[0];
                exch[r0*33 + cb + 9]       = s1[1];
                exch[(r0+8)*33 + cb + 8]   = s1[2];
                exch[(r0+8)*33 + cb + 9]   = s1[3];
            }
            __syncthreads();
        }

#pragma unroll
        for (int j = 0; j < 2; j++){
            int u = pu + j;
            float4 g = *(const float4*)&d_G[((size_t)t*Bb + pb)*NG + c0 + 4*u];
            float zf = g.x, zi = g.y, zo = g.z, za = g.w;
            if (t > 0){
                zf += exch[pb*33 + 4*u];
                zi += exch[pb*33 + 4*u + 1];
                zo += exch[pb*33 + 4*u + 2];
                za += exch[pb*33 + 4*u + 3];
            }
            float f  = 1.f/(1.f+expf(-zf));
            float i2 = 1.f/(1.f+expf(-zi));
            float o  = 1.f/(1.f+expf(-zo));
            float cc = i2*tanhf(za) + f*cst[j];
            cst[j] = cc;
            float hv = o*tanhf(cc);
            __nv_bfloat16 hb = __float2bfloat16_rn(hv);
            size_t hoff = ((size_t)t*Bb + pb)*Hh + u0 + u;
            d_Hallhi[hoff] = hb;
            d_Halllo[hoff] = __float2bfloat16_rn(hv - __bfloat162float(hb));
        }
        grid_bar((unsigned)(t+1) * NBLK);
    }
}

// ---- launch ----
extern "C" void kernel_launch(void* const* d_in, const int* in_sizes, int n_in,
                              void* d_out, int out_size){
    (void)in_sizes; (void)n_in; (void)out_size;
    const float* x     = (const float*)d_in[0];
    const float* wfx_w = (const float*)d_in[1];
    const float* wfx_b = (const float*)d_in[2];
    const float* wix_w = (const float*)d_in[3];
    const float* wix_b = (const float*)d_in[4];
    const float* wox_w = (const float*)d_in[5];
    const float* wox_b = (const float*)d_in[6];
    const float* wcx_w = (const float*)d_in[7];
    const float* wcx_b = (const float*)d_in[8];
    const float* ufh_w = (const float*)d_in[9];
    const float* uih_w = (const float*)d_in[10];
    const float* uoh_w = (const float*)d_in[11];
    const float* uch_w = (const float*)d_in[12];
    const float* fco_w = (const float*)d_in[13];
    const float* fco_b = (const float*)d_in[14];
    float* out = (float*)d_out;

    cudaFuncSetAttribute(k_recur_mma, cudaFuncAttributeMaxDynamicSharedMemorySize, RSMEM);
    cudaFuncSetAttribute(k_gemm_in_mma, cudaFuncAttributeMaxDynamicSharedMemorySize, ISMEM);
    cudaFuncSetAttribute(k_gemm_out_mma, cudaFuncAttributeMaxDynamicSharedMemorySize, ISMEM);

    k_build_wbf<<<(Ff*NG + 255)/256, 256>>>(wfx_w, wix_w, wox_w, wcx_w);
    k_split_x<<<(TBm*Ff + 255)/256, 256>>>(x);
    k_build_u<<<(Hh*NG + 255)/256, 256>>>(ufh_w, uih_w, uoh_w, uch_w);
    k_build_wout<<<(Hh*NOP + 255)/256, 256>>>(fco_w);
    k_build_misc<<<(NG + 255)/256, 256>>>(wfx_b, wix_b, wox_b, wcx_b);

    k_gemm_in_mma<<<dim3(NG/128, TBm/128), 256, ISMEM>>>();

    k_recur_mma<<<NBLK, 256, RSMEM>>>();

    k_gemm_out_mma<<<dim3(NOP/128, TBm/128), 256, ISMEM>>>(fco_b, out);
}

// round 10
// speedup vs baseline: 1.2099x; 1.2099x over previous
#include <cuda_runtime.h>
#include <cuda_bf16.h>
#include <cstdint>
#include <math.h>

#define Tt 128
#define Bb 64
#define Ff 512
#define Hh 1024
#define NG 4096
#define TBm 8192
#define OUTF 513
#define NOP 640           // padded output cols
#define NBLK 128

static __device__ float d_Bcat[NG];
static __device__ float d_G[(size_t)TBm*NG];
static __device__ __nv_bfloat16 d_Wbhi[(size_t)Ff*NG];
static __device__ __nv_bfloat16 d_Wblo[(size_t)Ff*NG];
static __device__ __nv_bfloat16 d_Xhi[(size_t)TBm*Ff];
static __device__ __nv_bfloat16 d_Xlo[(size_t)TBm*Ff];
static __device__ __nv_bfloat16 d_Ubhi[(size_t)Hh*NG];
static __device__ __nv_bfloat16 d_Ublo[(size_t)Hh*NG];
static __device__ __nv_bfloat16 d_Hallhi[(size_t)TBm*Hh];
static __device__ __nv_bfloat16 d_Halllo[(size_t)TBm*Hh];
static __device__ __nv_bfloat16 d_WoP_hi[(size_t)Hh*NOP];
static __device__ __nv_bfloat16 d_WoP_lo[(size_t)Hh*NOP];
static __device__ unsigned g_bar;

__constant__ int   c_CM[16] = {0,1,2,3, 1,0,3,2, 2,3,0,1, 3,2,1,0};
__constant__ float c_SG[16] = {1,1,1,1, -1,1,1,-1, -1,-1,1,1, -1,1,-1,1};

// ---- PTX helpers (sm_80-baseline, valid on sm_103) ----
__device__ __forceinline__ uint32_t smem_u32(const void* p){
    uint32_t a; asm("{ .reg .u64 t; cvta.to.shared.u64 t, %1; cvt.u32.u64 %0, t; }":"=r"(a):"l"(p)); return a;
}
#define LDSM4(r,a) asm volatile("ldmatrix.sync.aligned.m8n8.x4.shared.b16 {%0,%1,%2,%3}, [%4];" \
    :"=r"((r)[0]),"=r"((r)[1]),"=r"((r)[2]),"=r"((r)[3]):"r"(a))
#define LDSM4T(r,a) asm volatile("ldmatrix.sync.aligned.m8n8.x4.trans.shared.b16 {%0,%1,%2,%3}, [%4];" \
    :"=r"((r)[0]),"=r"((r)[1]),"=r"((r)[2]),"=r"((r)[3]):"r"(a))
#define MMA16816(c,a,b0,b1) asm volatile( \
    "mma.sync.aligned.m16n8k16.row.col.f32.bf16.bf16.f32 {%0,%1,%2,%3},{%4,%5,%6,%7},{%8,%9},{%0,%1,%2,%3};" \
    :"+f"((c)[0]),"+f"((c)[1]),"+f"((c)[2]),"+f"((c)[3]) \
    :"r"((a)[0]),"r"((a)[1]),"r"((a)[2]),"r"((a)[3]),"r"(b0),"r"(b1))
#define CPA16(dst,src) asm volatile("cp.async.cg.shared.global [%0], [%1], 16;"::"r"(dst),"l"(src))
#define CPA_COMMIT()   asm volatile("cp.async.commit_group;":::"memory")
#define CPA_WAIT1()    asm volatile("cp.async.wait_group 1;":::"memory")
#define CPA_WAIT0()    asm volatile("cp.async.wait_group 0;":::"memory")

// ---- builds (gate-interleaved cols: col = 4h + g) ----
__global__ void k_build_wbf(const float* __restrict__ wf, const float* __restrict__ wi,
                            const float* __restrict__ wo, const float* __restrict__ wc){
    int idx = blockIdx.x*blockDim.x + threadIdx.x;
    if (idx >= Ff*NG) return;
    int k = idx >> 12, c = idx & (NG-1);
    int g = c & 3, hh = c >> 2;
    int cb = hh>>8, bbp = hh&255, rb = k>>7, aa = k&127;
    const float* w = (g==0)?wf:(g==1)?wi:(g==2)?wo:wc;
    int m = rb*4+cb;
    float v = c_SG[m]*w[((size_t)c_CM[m]*128+aa)*256+bbp];
    __nv_bfloat16 hi = __float2bfloat16_rn(v);
    d_Wbhi[idx] = hi;
    d_Wblo[idx] = __float2bfloat16_rn(v - __bfloat162float(hi));
}
__global__ void k_split_x(const float* __restrict__ x){
    int idx = blockIdx.x*blockDim.x + threadIdx.x;
    if (idx >= TBm*Ff) return;
    float v = x[idx];
    __nv_bfloat16 hi = __float2bfloat16_rn(v);
    d_Xhi[idx] = hi;
    d_Xlo[idx] = __float2bfloat16_rn(v - __bfloat162float(hi));
}
__global__ void k_build_u(const float* __restrict__ uf, const float* __restrict__ ui,
                          const float* __restrict__ uo, const float* __restrict__ uc){
    int idx = blockIdx.x*blockDim.x + threadIdx.x;
    if (idx >= Hh*NG) return;
    int k = idx >> 12, c = idx & (NG-1);
    int g = c & 3, hh = c >> 2;
    int cb = hh>>8, bbp = hh&255, rb = k>>8, aa = k&255;
    const float* u = (g==0)?uf:(g==1)?ui:(g==2)?uo:uc;
    int m = rb*4+cb;
    float v = c_SG[m]*u[((size_t)c_CM[m]*256+aa)*256+bbp];
    __nv_bfloat16 hi = __float2bfloat16_rn(v);
    d_Ubhi[idx] = hi;
    d_Ublo[idx] = __float2bfloat16_rn(v - __bfloat162float(hi));
}
__global__ void k_build_wout(const float* __restrict__ Wo){
    int idx = blockIdx.x*blockDim.x + threadIdx.x;
    if (idx >= Hh*NOP) return;
    int k = idx / NOP, n = idx % NOP;
    float v = (n < OUTF) ? Wo[(size_t)k*OUTF + n] : 0.f;
    __nv_bfloat16 hi = __float2bfloat16_rn(v);
    d_WoP_hi[idx] = hi;
    d_WoP_lo[idx] = __float2bfloat16_rn(v - __bfloat162float(hi));
}
__global__ void k_build_misc(const float* __restrict__ bf, const float* __restrict__ bi,
                             const float* __restrict__ bo, const float* __restrict__ bc){
    int idx = blockIdx.x*blockDim.x + threadIdx.x;
    if (idx == 0) g_bar = 0u;
    if (idx < NG){
        int g = idx & 3, hh = idx >> 2;
        const float* b = (g==0)?bf:(g==1)?bi:(g==2)?bo:bc;
        d_Bcat[idx] = b[hh];
    }
}

// ---- HMMA GEMM tiles: 128x128 block, K-chunk 64, 8 warps (4m x 2n) ----
#define IA_STR 144
#define IB_STR 272
#define IA_SZ  (128*IA_STR)
#define IB_SZ  (64*IB_STR)
#define IBUF   (2*IA_SZ + 2*IB_SZ)
#define ISMEM  (2*IBUF)

__device__ __forceinline__ void tile_load(char* buf,
        const __nv_bfloat16* Ahi, const __nv_bfloat16* Alo, int astride,
        const __nv_bfloat16* Bhi, const __nv_bfloat16* Blo, int bstride,
        int row0, int col0, int kc, int tid){
    const __nv_bfloat16* Ac[2] = {Ahi, Alo};
    const __nv_bfloat16* Bc[2] = {Bhi, Blo};
#pragma unroll
    for (int j = 0; j < 8; j++){
        int i = tid + j*256;
        int comp = i >> 10, rem = i & 1023, r = rem >> 3, s = rem & 7;
        const char* src = (const char*)(Ac[comp] + (size_t)(row0 + r)*astride + kc*64 + s*8);
        CPA16(smem_u32(buf + comp*IA_SZ + r*IA_STR + s*16), src);
    }
    char* bbuf = buf + 2*IA_SZ;
#pragma unroll
    for (int j = 0; j < 8; j++){
        int i = tid + j*256;
        int comp = i >> 10, rem = i & 1023, r = rem >> 4, s = rem & 15;
        const char* src = (const char*)(Bc[comp] + (size_t)(kc*64 + r)*bstride + col0 + s*8);
        CPA16(smem_u32(bbuf + comp*IB_SZ + r*IB_STR + s*16), src);
    }
    CPA_COMMIT();
}

__device__ __forceinline__ void tile_mma(char* abuf, char* bbuf, int wm, int wn, int lane,
                                         float acc[2][8][4]){
#pragma unroll
    for (int ks = 0; ks < 4; ks++){
        uint32_t ah[2][4], al[2][4], bh[4][4], bl[4][4];
#pragma unroll
        for (int mi = 0; mi < 2; mi++){
            uint32_t aoff = (wm*32 + mi*16 + (lane&15))*IA_STR + ks*32 + (lane>>4)*16;
            LDSM4(ah[mi], smem_u32(abuf + aoff));
            LDSM4(al[mi], smem_u32(abuf + IA_SZ + aoff));
        }
#pragma unroll
        for (int ni = 0; ni < 4; ni++){
            uint32_t boff = (ks*16 + (lane&15))*IB_STR + wn*128 + ni*32 + (lane>>4)*16;
            LDSM4T(bh[ni], smem_u32(bbuf + boff));
            LDSM4T(bl[ni], smem_u32(bbuf + IB_SZ + boff));
        }
#pragma unroll
        for (int mi = 0; mi < 2; mi++)
#pragma unroll
            for (int ni = 0; ni < 4; ni++){
                MMA16816(acc[mi][2*ni],   ah[mi], bh[ni][0], bh[ni][1]);
                MMA16816(acc[mi][2*ni],   ah[mi], bl[ni][0], bl[ni][1]);
                MMA16816(acc[mi][2*ni],   al[mi], bh[ni][0], bh[ni][1]);
                MMA16816(acc[mi][2*ni+1], ah[mi], bh[ni][2], bh[ni][3]);
                MMA16816(acc[mi][2*ni+1], ah[mi], bl[ni][2], bl[ni][3]);
                MMA16816(acc[mi][2*ni+1], al[mi], bh[ni][2], bh[ni][3]);
            }
    }
}

__global__ __launch_bounds__(256,1) void k_gemm_in_mma(){
    extern __shared__ char sm[];
    const int tid = threadIdx.x, lane = tid&31, w = tid>>5;
    const int wm = w&3, wn = w>>2;
    const int col0 = blockIdx.x*128, row0 = blockIdx.y*128;
    float acc[2][8][4];
#pragma unroll
    for (int mi=0;mi<2;mi++)
#pragma unroll
        for (int nj=0;nj<8;nj++)
#pragma unroll
            for (int q=0;q<4;q++) acc[mi][nj][q]=0.f;

    tile_load(sm, d_Xhi, d_Xlo, Ff, d_Wbhi, d_Wblo, NG, row0, col0, 0, tid);
    for (int kc = 0; kc < 8; kc++){
        if (kc < 7) tile_load(sm + ((kc+1)&1)*IBUF, d_Xhi, d_Xlo, Ff, d_Wbhi, d_Wblo, NG,
                              row0, col0, kc+1, tid);
        if (kc < 7) CPA_WAIT1(); else CPA_WAIT0();
        __syncthreads();
        char* abuf = sm + (kc&1)*IBUF;
        tile_mma(abuf, abuf + 2*IA_SZ, wm, wn, lane, acc);
        __syncthreads();
    }
#pragma unroll
    for (int mi = 0; mi < 2; mi++){
        int r = wm*32 + mi*16 + (lane>>2);
#pragma unroll
        for (int nj = 0; nj < 8; nj++){
            int c = col0 + wn*64 + nj*8 + (lane&3)*2;
            float2 bc = *(const float2*)&d_Bcat[c];
            size_t g0 = (size_t)(row0 + r)*NG + c;
            *(float2*)&d_G[g0] = make_float2(acc[mi][nj][0] + bc.x, acc[mi][nj][1] + bc.y);
            *(float2*)&d_G[g0 + 8*NG] = make_float2(acc[mi][nj][2] + bc.x, acc[mi][nj][3] + bc.y);
        }
    }
}

// ---- HMMA output GEMM: Out = Hall @ WoP + bias (N padded to 640) ----
// NOTE: OUTF=513 is odd -> Out rows only 4B-aligned; epilogue uses SCALAR stores.
__global__ __launch_bounds__(256,1) void k_gemm_out_mma(const float* __restrict__ bout,
                                                        float* __restrict__ Out){
    extern __shared__ char sm[];
    const int tid = threadIdx.x, lane = tid&31, w = tid>>5;
    const int wm = w&3, wn = w>>2;
    const int col0 = blockIdx.x*128, row0 = blockIdx.y*128;
    float acc[2][8][4];
#pragma unroll
    for (int mi=0;mi<2;mi++)
#pragma unroll
        for (int nj=0;nj<8;nj++)
#pragma unroll
            for (int q=0;q<4;q++) acc[mi][nj][q]=0.f;

    tile_load(sm, d_Hallhi, d_Halllo, Hh, d_WoP_hi, d_WoP_lo, NOP, row0, col0, 0, tid);
    for (int kc = 0; kc < 16; kc++){
        if (kc < 15) tile_load(sm + ((kc+1)&1)*IBUF, d_Hallhi, d_Halllo, Hh, d_WoP_hi, d_WoP_lo, NOP,
                               row0, col0, kc+1, tid);
        if (kc < 15) CPA_WAIT1(); else CPA_WAIT0();
        __syncthreads();
        char* abuf = sm + (kc&1)*IBUF;
        tile_mma(abuf, abuf + 2*IA_SZ, wm, wn, lane, acc);
        __syncthreads();
    }
#pragma unroll
    for (int mi = 0; mi < 2; mi++){
        int r = wm*32 + mi*16 + (lane>>2);
#pragma unroll
        for (int nj = 0; nj < 8; nj++){
            int c = col0 + wn*64 + nj*8 + (lane&3)*2;
#pragma unroll
            for (int e = 0; e < 2; e++){
                int cc = c + e;
                if (cc < OUTF){
                    float bc = bout[cc];
                    size_t o0 = (size_t)(row0 + r)*OUTF + cc;
                    Out[o0]            = acc[mi][nj][e]     + bc;
                    Out[o0 + 8*OUTF]   = acc[mi][nj][e + 2] + bc;
                }
            }
        }
    }
}

// ---- persistent HMMA recurrence (__ldcg register-prefetch staging, R7-proven) ----
#define OFF_ULO  81920
#define OFF_HS   163840
#define HS_BUF   18432
#define HS_COMP  9216
#define OFF_EX   200704
#define RSMEM    (200704 + 8448)

__device__ __forceinline__ void grid_bar(unsigned target){
    __syncthreads();
    if (threadIdx.x == 0){
        __threadfence();
        atomicAdd(&g_bar, 1u);
        while (*(volatile unsigned*)&g_bar < target) { }
        __threadfence();
    }
    __syncthreads();
}

__global__ __launch_bounds__(256,1) void k_recur_mma(){
    extern __shared__ char sm[];
    const int tid = threadIdx.x, lane = tid&31, w = tid>>5;
    const int blk = blockIdx.x;
    const int c0 = blk*32, u0 = blk*8;
    const int wm = w&3, wn = w>>2;
    char* UHI = sm;
    char* ULO = sm + OFF_ULO;
    char* HSB = sm + OFF_HS;
    float* exch = (float*)(sm + OFF_EX);

    for (int i = tid; i < 1024*4; i += 256){
        int k = i>>2, s = i&3;
        *(uint4*)(UHI + k*80 + s*16) =
            *(const uint4*)((const char*)(d_Ubhi + (size_t)k*NG + c0) + s*16);
        *(uint4*)(ULO + k*80 + s*16) =
            *(const uint4*)((const char*)(d_Ublo + (size_t)k*NG + c0) + s*16);
    }

    float cst[2] = {0.f, 0.f};
    const int pb = tid>>2;
    const int pu = (tid&3)*2;

    for (int t = 0; t < Tt; t++){
        if (t > 0){
            const char* hhi = (const char*)(d_Hallhi + ((size_t)(t-1)*Bb << 10));
            const char* hlo = (const char*)(d_Halllo + ((size_t)(t-1)*Bb << 10));
            // stage chunk 0 (__ldcg: bypass L1 — written by other SMs last step)
#pragma unroll
            for (int j = 0; j < 4; j++){
                int i = tid + j*256; int comp = i>>9, r = (i>>3)&63, s = i&7;
                uint4 v = __ldcg((const uint4*)((comp?hlo:hhi) + r*2048 + s*16));
                *(uint4*)(HSB + comp*HS_COMP + r*144 + s*16) = v;
            }
            __syncthreads();

            float acc[6][4];
#pragma unroll
            for (int p=0;p<6;p++)
#pragma unroll
                for (int q=0;q<4;q++) acc[p][q]=0.f;

            for (int kc = 0; kc < 16; kc++){
                uint4 pre[4];
                if (kc < 15){
#pragma unroll
                    for (int j = 0; j < 4; j++){
                        int i = tid + j*256; int comp = i>>9, r = (i>>3)&63, s = i&7;
                        pre[j] = __ldcg((const uint4*)((comp?hlo:hhi) + r*2048 + (kc+1)*128 + s*16));
                    }
                }
                char* hs = HSB + (kc&1)*HS_BUF;
#pragma unroll
                for (int ks = 0; ks < 4; ks++){
                    uint32_t ah[4], al[4], bh[4], bl[4];
                    uint32_t aoff = (wm*16 + (lane&15))*144 + ks*32 + (lane>>4)*16;
                    LDSM4(ah, smem_u32(hs + aoff));
                    LDSM4(al, smem_u32(hs + HS_COMP + aoff));
                    uint32_t brow = kc*64 + ks*16 + (lane&15);
                    uint32_t boff = brow*80 + wn*32 + (lane>>4)*16;
                    LDSM4T(bh, smem_u32(UHI + boff));
                    LDSM4T(bl, smem_u32(ULO + boff));
                    MMA16816(acc[0], ah, bh[0], bh[1]);
                    MMA16816(acc[1], ah, bl[0], bl[1]);
                    MMA16816(acc[2], al, bh[0], bh[1]);
                    MMA16816(acc[3], ah, bh[2], bh[3]);
                    MMA16816(acc[4], ah, bl[2], bl[3]);
                    MMA16816(acc[5], al, bh[2], bh[3]);
                }
                if (kc < 15){
                    char* nb = HSB + ((kc+1)&1)*HS_BUF;
#pragma unroll
                    for (int j = 0; j < 4; j++){
                        int i = tid + j*256; int comp = i>>9, r = (i>>3)&63, s = i&7;
                        *(uint4*)(nb + comp*HS_COMP + r*144 + s*16) = pre[j];
                    }
                    __syncthreads();
                }
            }
            {
                int r0 = wm*16 + (lane>>2);
                int cb = wn*16 + (lane&3)*2;
                float s0[4], s1[4];
#pragma unroll
                for (int q=0;q<4;q++){
                    s0[q] = acc[0][q] + acc[1][q] + acc[2][q];
                    s1[q] = acc[3][q] + acc[4][q] + acc[5][q];
                }
                exch[r0*33 + cb]       = s0[0];
                exch[r0*33 + cb + 1]   = s0[1];
                exch[(r0+8)*33 + cb]   = s0[2];
                exch[(r0+8)*33 + cb+1] = s0[3];
                exch[r0*33 + cb + 8]       = s1[0];
                exch[r0*33 + cb + 9]       = s1[1];
                exch[(r0+8)*33 + cb + 8]   = s1[2];
                exch[(r0+8)*33 + cb + 9]   = s1[3];
            }
            __syncthreads();
        }

#pragma unroll
        for (int j = 0; j < 2; j++){
            int u = pu + j;
            float4 g = *(const float4*)&d_G[((size_t)t*Bb + pb)*NG + c0 + 4*u];
            float zf = g.x, zi = g.y, zo = g.z, za = g.w;
            if (t > 0){
                zf += exch[pb*33 + 4*u];
                zi += exch[pb*33 + 4*u + 1];
                zo += exch[pb*33 + 4*u + 2];
                za += exch[pb*33 + 4*u + 3];
            }
            float f  = 1.f/(1.f+expf(-zf));
            float i2 = 1.f/(1.f+expf(-zi));
            float o  = 1.f/(1.f+expf(-zo));
            float cc = i2*tanhf(za) + f*cst[j];
            cst[j] = cc;
            float hv = o*tanhf(cc);
            __nv_bfloat16 hb = __float2bfloat16_rn(hv);
            size_t hoff = ((size_t)t*Bb + pb)*Hh + u0 + u;
            d_Hallhi[hoff] = hb;
            d_Halllo[hoff] = __float2bfloat16_rn(hv - __bfloat162float(hb));
        }
        grid_bar((unsigned)(t+1) * NBLK);
    }
}

// ---- launch ----
extern "C" void kernel_launch(void* const* d_in, const int* in_sizes, int n_in,
                              void* d_out, int out_size){
    (void)in_sizes; (void)n_in; (void)out_size;
    const float* x     = (const float*)d_in[0];
    const float* wfx_w = (const float*)d_in[1];
    const float* wfx_b = (const float*)d_in[2];
    const float* wix_w = (const float*)d_in[3];
    const float* wix_b = (const float*)d_in[4];
    const float* wox_w = (const float*)d_in[5];
    const float* wox_b = (const float*)d_in[6];
    const float* wcx_w = (const float*)d_in[7];
    const float* wcx_b = (const float*)d_in[8];
    const float* ufh_w = (const float*)d_in[9];
    const float* uih_w = (const float*)d_in[10];
    const float* uoh_w = (const float*)d_in[11];
    const float* uch_w = (const float*)d_in[12];
    const float* fco_w = (const float*)d_in[13];
    const float* fco_b = (const float*)d_in[14];
    float* out = (float*)d_out;

    cudaFuncSetAttribute(k_recur_mma, cudaFuncAttributeMaxDynamicSharedMemorySize, RSMEM);
    cudaFuncSetAttribute(k_gemm_in_mma, cudaFuncAttributeMaxDynamicSharedMemorySize, ISMEM);
    cudaFuncSetAttribute(k_gemm_out_mma, cudaFuncAttributeMaxDynamicSharedMemorySize, ISMEM);

    k_build_wbf<<<(Ff*NG + 255)/256, 256>>>(wfx_w, wix_w, wox_w, wcx_w);
    k_split_x<<<(TBm*Ff + 255)/256, 256>>>(x);
    k_build_u<<<(Hh*NG + 255)/256, 256>>>(ufh_w, uih_w, uoh_w, uch_w);
    k_build_wout<<<(Hh*NOP + 255)/256, 256>>>(fco_w);
    k_build_misc<<<(NG + 255)/256, 256>>>(wfx_b, wix_b, wox_b, wcx_b);

    k_gemm_in_mma<<<dim3(NG/128, TBm/128), 256, ISMEM>>>();

    k_recur_mma<<<NBLK, 256, RSMEM>>>();

    k_gemm_out_mma<<<dim3(NOP/128, TBm/128), 256, ISMEM>>>(fco_b, out);
}

// round 11
// speedup vs baseline: 1.3550x; 1.1199x over previous
#include <cuda_runtime.h>
#include <cuda_bf16.h>
#include <cuda_fp16.h>
#include <cstdint>
#include <math.h>

#define Tt 128
#define Bb 64
#define Ff 512
#define Hh 1024
#define NG 4096
#define TBm 8192
#define OUTF 513
#define NOP 640
#define NBLK 128

static __device__ float d_Bcat[NG];
static __device__ float d_G[(size_t)TBm*NG];
static __device__ __nv_bfloat16 d_Wbhi[(size_t)Ff*NG];
static __device__ __nv_bfloat16 d_Wblo[(size_t)Ff*NG];
static __device__ __nv_bfloat16 d_Xhi[(size_t)TBm*Ff];
static __device__ __nv_bfloat16 d_Xlo[(size_t)TBm*Ff];
static __device__ __half d_Uf16hi[(size_t)Hh*NG];
static __device__ __half d_Uf16lo[(size_t)Hh*NG];
static __device__ __half d_Hall16[(size_t)TBm*Hh];
static __device__ __half d_Wo16hi[(size_t)Hh*NOP];
static __device__ __half d_Wo16lo[(size_t)Hh*NOP];
static __device__ unsigned g_bar;

__constant__ int   c_CM[16] = {0,1,2,3, 1,0,3,2, 2,3,0,1, 3,2,1,0};
__constant__ float c_SG[16] = {1,1,1,1, -1,1,1,-1, -1,-1,1,1, -1,1,-1,1};

// ---- PTX helpers (sm_80-baseline, valid on sm_103) ----
__device__ __forceinline__ uint32_t smem_u32(const void* p){
    uint32_t a; asm("{ .reg .u64 t; cvta.to.shared.u64 t, %1; cvt.u32.u64 %0, t; }":"=r"(a):"l"(p)); return a;
}
#define LDSM4(r,a) asm volatile("ldmatrix.sync.aligned.m8n8.x4.shared.b16 {%0,%1,%2,%3}, [%4];" \
    :"=r"((r)[0]),"=r"((r)[1]),"=r"((r)[2]),"=r"((r)[3]):"r"(a))
#define LDSM4T(r,a) asm volatile("ldmatrix.sync.aligned.m8n8.x4.trans.shared.b16 {%0,%1,%2,%3}, [%4];" \
    :"=r"((r)[0]),"=r"((r)[1]),"=r"((r)[2]),"=r"((r)[3]):"r"(a))
#define MMABF16(c,a,b0,b1) asm volatile( \
    "mma.sync.aligned.m16n8k16.row.col.f32.bf16.bf16.f32 {%0,%1,%2,%3},{%4,%5,%6,%7},{%8,%9},{%0,%1,%2,%3};" \
    :"+f"((c)[0]),"+f"((c)[1]),"+f"((c)[2]),"+f"((c)[3]) \
    :"r"((a)[0]),"r"((a)[1]),"r"((a)[2]),"r"((a)[3]),"r"(b0),"r"(b1))
#define MMAF16(c,a,b0,b1) asm volatile( \
    "mma.sync.aligned.m16n8k16.row.col.f32.f16.f16.f32 {%0,%1,%2,%3},{%4,%5,%6,%7},{%8,%9},{%0,%1,%2,%3};" \
    :"+f"((c)[0]),"+f"((c)[1]),"+f"((c)[2]),"+f"((c)[3]) \
    :"r"((a)[0]),"r"((a)[1]),"r"((a)[2]),"r"((a)[3]),"r"(b0),"r"(b1))
#define CPA16(dst,src) asm volatile("cp.async.cg.shared.global [%0], [%1], 16;"::"r"(dst),"l"(src))
#define CPA_COMMIT()   asm volatile("cp.async.commit_group;":::"memory")
#define CPA_WAIT1()    asm volatile("cp.async.wait_group 1;":::"memory")
#define CPA_WAIT0()    asm volatile("cp.async.wait_group 0;":::"memory")

// ---- builds (gate-interleaved cols: col = 4h + g) ----
__global__ void k_build_wbf(const float* __restrict__ wf, const float* __restrict__ wi,
                            const float* __restrict__ wo, const float* __restrict__ wc){
    int idx = blockIdx.x*blockDim.x + threadIdx.x;
    if (idx >= Ff*NG) return;
    int k = idx >> 12, c = idx & (NG-1);
    int g = c & 3, hh = c >> 2;
    int cb = hh>>8, bbp = hh&255, rb = k>>7, aa = k&127;
    const float* w = (g==0)?wf:(g==1)?wi:(g==2)?wo:wc;
    int m = rb*4+cb;
    float v = c_SG[m]*w[((size_t)c_CM[m]*128+aa)*256+bbp];
    __nv_bfloat16 hi = __float2bfloat16_rn(v);
    d_Wbhi[idx] = hi;
    d_Wblo[idx] = __float2bfloat16_rn(v - __bfloat162float(hi));
}
__global__ void k_split_x(const float* __restrict__ x){
    int idx = blockIdx.x*blockDim.x + threadIdx.x;
    if (idx >= TBm*Ff) return;
    float v = x[idx];
    __nv_bfloat16 hi = __float2bfloat16_rn(v);
    d_Xhi[idx] = hi;
    d_Xlo[idx] = __float2bfloat16_rn(v - __bfloat162float(hi));
}
__global__ void k_build_u(const float* __restrict__ uf, const float* __restrict__ ui,
                          const float* __restrict__ uo, const float* __restrict__ uc){
    int idx = blockIdx.x*blockDim.x + threadIdx.x;
    if (idx >= Hh*NG) return;
    int k = idx >> 12, c = idx & (NG-1);
    int g = c & 3, hh = c >> 2;
    int cb = hh>>8, bbp = hh&255, rb = k>>8, aa = k&255;
    const float* u = (g==0)?uf:(g==1)?ui:(g==2)?uo:uc;
    int m = rb*4+cb;
    float v = c_SG[m]*u[((size_t)c_CM[m]*256+aa)*256+bbp];
    __half hi = __float2half_rn(v);
    d_Uf16hi[idx] = hi;
    d_Uf16lo[idx] = __float2half_rn(v - __half2float(hi));
}
__global__ void k_build_wout(const float* __restrict__ Wo){
    int idx = blockIdx.x*blockDim.x + threadIdx.x;
    if (idx >= Hh*NOP) return;
    int k = idx / NOP, n = idx % NOP;
    float v = (n < OUTF) ? Wo[(size_t)k*OUTF + n] : 0.f;
    __half hi = __float2half_rn(v);
    d_Wo16hi[idx] = hi;
    d_Wo16lo[idx] = __float2half_rn(v - __half2float(hi));
}
__global__ void k_build_misc(const float* __restrict__ bf, const float* __restrict__ bi,
                             const float* __restrict__ bo, const float* __restrict__ bc){
    int idx = blockIdx.x*blockDim.x + threadIdx.x;
    if (idx == 0) g_bar = 0u;
    if (idx < NG){
        int g = idx & 3, hh = idx >> 2;
        const float* b = (g==0)?bf:(g==1)?bi:(g==2)?bo:bc;
        d_Bcat[idx] = b[hh];
    }
}

// ---- HMMA input GEMM (bf16, 3-product, proven) ----
#define IA_STR 144
#define IB_STR 272
#define IA_SZ  (128*IA_STR)
#define IB_SZ  (64*IB_STR)
#define IBUF   (2*IA_SZ + 2*IB_SZ)
#define ISMEM  (2*IBUF)

__device__ __forceinline__ void gi_load(char* buf, int row0, int col0, int kc, int tid){
    const __nv_bfloat16* Ac[2] = {d_Xhi, d_Xlo};
    const __nv_bfloat16* Bc[2] = {d_Wbhi, d_Wblo};
#pragma unroll
    for (int j = 0; j < 8; j++){
        int i = tid + j*256;
        int comp = i >> 10, rem = i & 1023, r = rem >> 3, s = rem & 7;
        const char* src = (const char*)(Ac[comp] + (size_t)(row0 + r)*Ff + kc*64 + s*8);
        CPA16(smem_u32(buf + comp*IA_SZ + r*IA_STR + s*16), src);
    }
    char* bbuf = buf + 2*IA_SZ;
#pragma unroll
    for (int j = 0; j < 8; j++){
        int i = tid + j*256;
        int comp = i >> 10, rem = i & 1023, r = rem >> 4, s = rem & 15;
        const char* src = (const char*)(Bc[comp] + (size_t)(kc*64 + r)*NG + col0 + s*8);
        CPA16(smem_u32(bbuf + comp*IB_SZ + r*IB_STR + s*16), src);
    }
    CPA_COMMIT();
}

__global__ __launch_bounds__(256,1) void k_gemm_in_mma(){
    extern __shared__ char sm[];
    const int tid = threadIdx.x, lane = tid&31, w = tid>>5;
    const int wm = w&3, wn = w>>2;
    const int col0 = blockIdx.x*128, row0 = blockIdx.y*128;
    float acc[2][8][4];
#pragma unroll
    for (int mi=0;mi<2;mi++)
#pragma unroll
        for (int nj=0;nj<8;nj++)
#pragma unroll
            for (int q=0;q<4;q++) acc[mi][nj][q]=0.f;

    gi_load(sm, row0, col0, 0, tid);
    for (int kc = 0; kc < 8; kc++){
        if (kc < 7) gi_load(sm + ((kc+1)&1)*IBUF, row0, col0, kc+1, tid);
        if (kc < 7) CPA_WAIT1(); else CPA_WAIT0();
        __syncthreads();
        char* abuf = sm + (kc&1)*IBUF;
        char* bbuf = abuf + 2*IA_SZ;
#pragma unroll
        for (int ks = 0; ks < 4; ks++){
            uint32_t ah[2][4], al[2][4], bh[4][4], bl[4][4];
#pragma unroll
            for (int mi = 0; mi < 2; mi++){
                uint32_t aoff = (wm*32 + mi*16 + (lane&15))*IA_STR + ks*32 + (lane>>4)*16;
                LDSM4(ah[mi], smem_u32(abuf + aoff));
                LDSM4(al[mi], smem_u32(abuf + IA_SZ + aoff));
            }
#pragma unroll
            for (int ni = 0; ni < 4; ni++){
                uint32_t boff = (ks*16 + (lane&15))*IB_STR + wn*128 + ni*32 + (lane>>4)*16;
                LDSM4T(bh[ni], smem_u32(bbuf + boff));
                LDSM4T(bl[ni], smem_u32(bbuf + IB_SZ + boff));
            }
#pragma unroll
            for (int mi = 0; mi < 2; mi++)
#pragma unroll
                for (int ni = 0; ni < 4; ni++){
                    MMABF16(acc[mi][2*ni],   ah[mi], bh[ni][0], bh[ni][1]);
                    MMABF16(acc[mi][2*ni],   ah[mi], bl[ni][0], bl[ni][1]);
                    MMABF16(acc[mi][2*ni],   al[mi], bh[ni][0], bh[ni][1]);
                    MMABF16(acc[mi][2*ni+1], ah[mi], bh[ni][2], bh[ni][3]);
                    MMABF16(acc[mi][2*ni+1], ah[mi], bl[ni][2], bl[ni][3]);
                    MMABF16(acc[mi][2*ni+1], al[mi], bh[ni][2], bh[ni][3]);
                }
        }
        __syncthreads();
    }
#pragma unroll
    for (int mi = 0; mi < 2; mi++){
        int r = wm*32 + mi*16 + (lane>>2);
#pragma unroll
        for (int nj = 0; nj < 8; nj++){
            int c = col0 + wn*64 + nj*8 + (lane&3)*2;
            float2 bc = *(const float2*)&d_Bcat[c];
            size_t g0 = (size_t)(row0 + r)*NG + c;
            *(float2*)&d_G[g0] = make_float2(acc[mi][nj][0] + bc.x, acc[mi][nj][1] + bc.y);
            *(float2*)&d_G[g0 + 8*NG] = make_float2(acc[mi][nj][2] + bc.x, acc[mi][nj][3] + bc.y);
        }
    }
}

// ---- HMMA output GEMM (fp16: A = Hall16 single, B = Wo16 hi/lo, 2 products) ----
#define OA_SZ  (128*IA_STR)
#define OBUF   (OA_SZ + 2*IB_SZ)
#define OSMEM  (2*OBUF)

__device__ __forceinline__ void go_load(char* buf, int row0, int col0, int kc, int tid){
#pragma unroll
    for (int j = 0; j < 4; j++){
        int i = tid + j*256;
        int r = i >> 3, s = i & 7;
        const char* src = (const char*)(d_Hall16 + (size_t)(row0 + r)*Hh + kc*64 + s*8);
        CPA16(smem_u32(buf + r*IA_STR + s*16), src);
    }
    char* bbuf = buf + OA_SZ;
    const __half* Bc[2] = {d_Wo16hi, d_Wo16lo};
#pragma unroll
    for (int j = 0; j < 8; j++){
        int i = tid + j*256;
        int comp = i >> 10, rem = i & 1023, r = rem >> 4, s = rem & 15;
        const char* src = (const char*)(Bc[comp] + (size_t)(kc*64 + r)*NOP + col0 + s*8);
        CPA16(smem_u32(bbuf + comp*IB_SZ + r*IB_STR + s*16), src);
    }
    CPA_COMMIT();
}

__global__ __launch_bounds__(256,1) void k_gemm_out_mma(const float* __restrict__ bout,
                                                        float* __restrict__ Out){
    extern __shared__ char sm[];
    const int tid = threadIdx.x, lane = tid&31, w = tid>>5;
    const int wm = w&3, wn = w>>2;
    const int col0 = blockIdx.x*128, row0 = blockIdx.y*128;
    float acc[2][8][4];
#pragma unroll
    for (int mi=0;mi<2;mi++)
#pragma unroll
        for (int nj=0;nj<8;nj++)
#pragma unroll
            for (int q=0;q<4;q++) acc[mi][nj][q]=0.f;

    go_load(sm, row0, col0, 0, tid);
    for (int kc = 0; kc < 16; kc++){
        if (kc < 15) go_load(sm + ((kc+1)&1)*OBUF, row0, col0, kc+1, tid);
        if (kc < 15) CPA_WAIT1(); else CPA_WAIT0();
        __syncthreads();
        char* abuf = sm + (kc&1)*OBUF;
        char* bbuf = abuf + OA_SZ;
#pragma unroll
        for (int ks = 0; ks < 4; ks++){
            uint32_t ah[2][4], bh[4][4], bl[4][4];
#pragma unroll
            for (int mi = 0; mi < 2; mi++){
                uint32_t aoff = (wm*32 + mi*16 + (lane&15))*IA_STR + ks*32 + (lane>>4)*16;
                LDSM4(ah[mi], smem_u32(abuf + aoff));
            }
#pragma unroll
            for (int ni = 0; ni < 4; ni++){
                uint32_t boff = (ks*16 + (lane&15))*IB_STR + wn*128 + ni*32 + (lane>>4)*16;
                LDSM4T(bh[ni], smem_u32(bbuf + boff));
                LDSM4T(bl[ni], smem_u32(bbuf + IB_SZ + boff));
            }
#pragma unroll
            for (int mi = 0; mi < 2; mi++)
#pragma unroll
                for (int ni = 0; ni < 4; ni++){
                    MMAF16(acc[mi][2*ni],   ah[mi], bh[ni][0], bh[ni][1]);
                    MMAF16(acc[mi][2*ni],   ah[mi], bl[ni][0], bl[ni][1]);
                    MMAF16(acc[mi][2*ni+1], ah[mi], bh[ni][2], bh[ni][3]);
                    MMAF16(acc[mi][2*ni+1], ah[mi], bl[ni][2], bl[ni][3]);
                }
        }
        __syncthreads();
    }
    // scalar stores: OUTF=513 is odd, rows only 4B-aligned
#pragma unroll
    for (int mi = 0; mi < 2; mi++){
        int r = wm*32 + mi*16 + (lane>>2);
#pragma unroll
        for (int nj = 0; nj < 8; nj++){
            int c = col0 + wn*64 + nj*8 + (lane&3)*2;
#pragma unroll
            for (int e = 0; e < 2; e++){
                int cc = c + e;
                if (cc < OUTF){
                    float bc = bout[cc];
                    size_t o0 = (size_t)(row0 + r)*OUTF + cc;
                    Out[o0]          = acc[mi][nj][e]     + bc;
                    Out[o0 + 8*OUTF] = acc[mi][nj][e + 2] + bc;
                }
            }
        }
    }
}

// ---- persistent HMMA recurrence (fp16 h single-comp, U fp16 hi/lo, 2 products) ----
#define OFF_ULO  81920
#define OFF_HS   163840
#define HS_BUF   9216
#define OFF_EX   182272
#define RSMEM    (182272 + 8448)

__device__ __forceinline__ void grid_bar(unsigned target){
    __syncthreads();
    if (threadIdx.x == 0){
        __threadfence();
        atomicAdd(&g_bar, 1u);
        while (*(volatile unsigned*)&g_bar < target) { }
        __threadfence();
    }
    __syncthreads();
}

__global__ __launch_bounds__(256,1) void k_recur_mma(){
    extern __shared__ char sm[];
    const int tid = threadIdx.x, lane = tid&31, w = tid>>5;
    const int blk = blockIdx.x;
    const int c0 = blk*32, u0 = blk*8;
    const int wm = w&3, wn = w>>2;
    char* UHI = sm;
    char* ULO = sm + OFF_ULO;
    char* HSB = sm + OFF_HS;
    float* exch = (float*)(sm + OFF_EX);

    // resident U slice (fp16 hi/lo), padded 80B rows
    for (int i = tid; i < 1024*4; i += 256){
        int k = i>>2, s = i&3;
        *(uint4*)(UHI + k*80 + s*16) =
            *(const uint4*)((const char*)(d_Uf16hi + (size_t)k*NG + c0) + s*16);
        *(uint4*)(ULO + k*80 + s*16) =
            *(const uint4*)((const char*)(d_Uf16lo + (size_t)k*NG + c0) + s*16);
    }

    float cst[2] = {0.f, 0.f};
    const int pb = tid>>2;
    const int pu = (tid&3)*2;

    for (int t = 0; t < Tt; t++){
        if (t > 0){
            const char* hsrc = (const char*)(d_Hall16 + ((size_t)(t-1)*Bb << 10));
            // stage chunk 0 (__ldcg: written by other SMs last step)
#pragma unroll
            for (int j = 0; j < 2; j++){
                int i = tid + j*256; int r = i>>3, s = i&7;
                uint4 v = __ldcg((const uint4*)(hsrc + r*2048 + s*16));
                *(uint4*)(HSB + r*144 + s*16) = v;
            }
            __syncthreads();

            float accP[2][4], accQ[2][4];
#pragma unroll
            for (int p=0;p<2;p++)
#pragma unroll
                for (int q=0;q<4;q++){ accP[p][q]=0.f; accQ[p][q]=0.f; }

            for (int kc = 0; kc < 16; kc++){
                uint4 pre[2];
                if (kc < 15){
#pragma unroll
                    for (int j = 0; j < 2; j++){
                        int i = tid + j*256; int r = i>>3, s = i&7;
                        pre[j] = __ldcg((const uint4*)(hsrc + r*2048 + (kc+1)*128 + s*16));
                    }
                }
                char* hs = HSB + (kc&1)*HS_BUF;
#pragma unroll
                for (int ks = 0; ks < 4; ks++){
                    uint32_t ah[4], bh[4], bl[4];
                    uint32_t aoff = (wm*16 + (lane&15))*144 + ks*32 + (lane>>4)*16;
                    LDSM4(ah, smem_u32(hs + aoff));
                    uint32_t brow = kc*64 + ks*16 + (lane&15);
                    uint32_t boff = brow*80 + wn*32 + (lane>>4)*16;
                    LDSM4T(bh, smem_u32(UHI + boff));
                    LDSM4T(bl, smem_u32(ULO + boff));
                    MMAF16(accP[0], ah, bh[0], bh[1]);
                    MMAF16(accP[1], ah, bh[2], bh[3]);
                    MMAF16(accQ[0], ah, bl[0], bl[1]);
                    MMAF16(accQ[1], ah, bl[2], bl[3]);
                }
                if (kc < 15){
                    char* nb = HSB + ((kc+1)&1)*HS_BUF;
#pragma unroll
                    for (int j = 0; j < 2; j++){
                        int i = tid + j*256; int r = i>>3, s = i&7;
                        *(uint4*)(nb + r*144 + s*16) = pre[j];
                    }
                    __syncthreads();
                }
            }
            {
                int r0 = wm*16 + (lane>>2);
                int cb = wn*16 + (lane&3)*2;
                float s0[4], s1[4];
#pragma unroll
                for (int q=0;q<4;q++){
                    s0[q] = accP[0][q] + accQ[0][q];
                    s1[q] = accP[1][q] + accQ[1][q];
                }
                exch[r0*33 + cb]       = s0[0];
                exch[r0*33 + cb + 1]   = s0[1];
                exch[(r0+8)*33 + cb]   = s0[2];
                exch[(r0+8)*33 + cb+1] = s0[3];
                exch[r0*33 + cb + 8]       = s1[0];
                exch[r0*33 + cb + 9]       = s1[1];
                exch[(r0+8)*33 + cb + 8]   = s1[2];
                exch[(r0+8)*33 + cb + 9]   = s1[3];
            }
            __syncthreads();
        }

#pragma unroll
        for (int j = 0; j < 2; j++){
            int u = pu + j;
            float4 g = *(const float4*)&d_G[((size_t)t*Bb + pb)*NG + c0 + 4*u];
            float zf = g.x, zi = g.y, zo = g.z, za = g.w;
            if (t > 0){
                zf += exch[pb*33 + 4*u];
                zi += exch[pb*33 + 4*u + 1];
                zo += exch[pb*33 + 4*u + 2];
                za += exch[pb*33 + 4*u + 3];
            }
            float f  = 1.f/(1.f+expf(-zf));
            float i2 = 1.f/(1.f+expf(-zi));
            float o  = 1.f/(1.f+expf(-zo));
            float cc = i2*tanhf(za) + f*cst[j];
            cst[j] = cc;
            float hv = o*tanhf(cc);
            d_Hall16[((size_t)t*Bb + pb)*Hh + u0 + u] = __float2half_rn(hv);
        }
        grid_bar((unsigned)(t+1) * NBLK);
    }
}

// ---- launch ----
extern "C" void kernel_launch(void* const* d_in, const int* in_sizes, int n_in,
                              void* d_out, int out_size){
    (void)in_sizes; (void)n_in; (void)out_size;
    const float* x     = (const float*)d_in[0];
    const float* wfx_w = (const float*)d_in[1];
    const float* wfx_b = (const float*)d_in[2];
    const float* wix_w = (const float*)d_in[3];
    const float* wix_b = (const float*)d_in[4];
    const float* wox_w = (const float*)d_in[5];
    const float* wox_b = (const float*)d_in[6];
    const float* wcx_w = (const float*)d_in[7];
    const float* wcx_b = (const float*)d_in[8];
    const float* ufh_w = (const float*)d_in[9];
    const float* uih_w = (const float*)d_in[10];
    const float* uoh_w = (const float*)d_in[11];
    const float* uch_w = (const float*)d_in[12];
    const float* fco_w = (const float*)d_in[13];
    const float* fco_b = (const float*)d_in[14];
    float* out = (float*)d_out;

    cudaFuncSetAttribute(k_recur_mma, cudaFuncAttributeMaxDynamicSharedMemorySize, RSMEM);
    cudaFuncSetAttribute(k_gemm_in_mma, cudaFuncAttributeMaxDynamicSharedMemorySize, ISMEM);
    cudaFuncSetAttribute(k_gemm_out_mma, cudaFuncAttributeMaxDynamicSharedMemorySize, OSMEM);

    k_build_wbf<<<(Ff*NG + 255)/256, 256>>>(wfx_w, wix_w, wox_w, wcx_w);
    k_split_x<<<(TBm*Ff + 255)/256, 256>>>(x);
    k_build_u<<<(Hh*NG + 255)/256, 256>>>(ufh_w, uih_w, uoh_w, uch_w);
    k_build_wout<<<(Hh*NOP + 255)/256, 256>>>(fco_w);
    k_build_misc<<<(NG + 255)/256, 256>>>(wfx_b, wix_b, wox_b, wcx_b);

    k_gemm_in_mma<<<dim3(NG/128, TBm/128), 256, ISMEM>>>();

    k_recur_mma<<<NBLK, 256, RSMEM>>>();

    k_gemm_out_mma<<<dim3(NOP/128, TBm/128), 256, OSMEM>>>(fco_b, out);
}

// round 13
// speedup vs baseline: 1.4651x; 1.0813x over previous
#include <cuda_runtime.h>
#include <cuda_bf16.h>
#include <cuda_fp16.h>
#include <cstdint>
#include <math.h>

#define Tt 128
#define Bb 64
#define Ff 512
#define Hh 1024
#define NG 4096
#define TBm 8192
#define OUTF 513
#define NOP 640
#define NBLK 128

static __device__ float d_Bcat[NG];
static __device__ float d_G[(size_t)TBm*NG];
static __device__ __nv_bfloat16 d_Wbhi[(size_t)Ff*NG];
static __device__ __nv_bfloat16 d_Wblo[(size_t)Ff*NG];
static __device__ __nv_bfloat16 d_Xhi[(size_t)TBm*Ff];
static __device__ __nv_bfloat16 d_Xlo[(size_t)TBm*Ff];
static __device__ __half d_Uf16hi[(size_t)Hh*NG];
static __device__ __half d_Uf16lo[(size_t)Hh*NG];
static __device__ __half d_Hall16[(size_t)TBm*Hh];
static __device__ __half d_Wo16hi[(size_t)Hh*NOP];
static __device__ __half d_Wo16lo[(size_t)Hh*NOP];
static __device__ unsigned g_bar;

__constant__ int   c_CM[16] = {0,1,2,3, 1,0,3,2, 2,3,0,1, 3,2,1,0};
__constant__ float c_SG[16] = {1,1,1,1, -1,1,1,-1, -1,-1,1,1, -1,1,-1,1};

// ---- PTX helpers (sm_80-baseline, valid on sm_103) ----
__device__ __forceinline__ uint32_t smem_u32(const void* p){
    uint32_t a; asm("{ .reg .u64 t; cvta.to.shared.u64 t, %1; cvt.u32.u64 %0, t; }":"=r"(a):"l"(p)); return a;
}
#define LDSM4(r,a) asm volatile("ldmatrix.sync.aligned.m8n8.x4.shared.b16 {%0,%1,%2,%3}, [%4];" \
    :"=r"((r)[0]),"=r"((r)[1]),"=r"((r)[2]),"=r"((r)[3]):"r"(a))
#define LDSM4T(r,a) asm volatile("ldmatrix.sync.aligned.m8n8.x4.trans.shared.b16 {%0,%1,%2,%3}, [%4];" \
    :"=r"((r)[0]),"=r"((r)[1]),"=r"((r)[2]),"=r"((r)[3]):"r"(a))
#define MMABF16(c,a,b0,b1) asm volatile( \
    "mma.sync.aligned.m16n8k16.row.col.f32.bf16.bf16.f32 {%0,%1,%2,%3},{%4,%5,%6,%7},{%8,%9},{%0,%1,%2,%3};" \
    :"+f"((c)[0]),"+f"((c)[1]),"+f"((c)[2]),"+f"((c)[3]) \
    :"r"((a)[0]),"r"((a)[1]),"r"((a)[2]),"r"((a)[3]),"r"(b0),"r"(b1))
#define MMAF16(c,a,b0,b1) asm volatile( \
    "mma.sync.aligned.m16n8k16.row.col.f32.f16.f16.f32 {%0,%1,%2,%3},{%4,%5,%6,%7},{%8,%9},{%0,%1,%2,%3};" \
    :"+f"((c)[0]),"+f"((c)[1]),"+f"((c)[2]),"+f"((c)[3]) \
    :"r"((a)[0]),"r"((a)[1]),"r"((a)[2]),"r"((a)[3]),"r"(b0),"r"(b1))
#define CPA16(dst,src) asm volatile("cp.async.cg.shared.global [%0], [%1], 16;"::"r"(dst),"l"(src))
#define CPA_COMMIT()   asm volatile("cp.async.commit_group;":::"memory")
#define CPA_WAIT1()    asm volatile("cp.async.wait_group 1;":::"memory")
#define CPA_WAIT0()    asm volatile("cp.async.wait_group 0;":::"memory")

// ---- builds (gate-interleaved cols: col = 4h + g) ----
__global__ void k_build_wbf(const float* __restrict__ wf, const float* __restrict__ wi,
                            const float* __restrict__ wo, const float* __restrict__ wc){
    int idx = blockIdx.x*blockDim.x + threadIdx.x;
    if (idx >= Ff*NG) return;
    int k = idx >> 12, c = idx & (NG-1);
    int g = c & 3, hh = c >> 2;
    int cb = hh>>8, bbp = hh&255, rb = k>>7, aa = k&127;
    const float* w = (g==0)?wf:(g==1)?wi:(g==2)?wo:wc;
    int m = rb*4+cb;
    float v = c_SG[m]*w[((size_t)c_CM[m]*128+aa)*256+bbp];
    __nv_bfloat16 hi = __float2bfloat16_rn(v);
    d_Wbhi[idx] = hi;
    d_Wblo[idx] = __float2bfloat16_rn(v - __bfloat162float(hi));
}
__global__ void k_split_x(const float* __restrict__ x){
    int idx = blockIdx.x*blockDim.x + threadIdx.x;
    if (idx >= TBm*Ff) return;
    float v = x[idx];
    __nv_bfloat16 hi = __float2bfloat16_rn(v);
    d_Xhi[idx] = hi;
    d_Xlo[idx] = __float2bfloat16_rn(v - __bfloat162float(hi));
}
__global__ void k_build_u(const float* __restrict__ uf, const float* __restrict__ ui,
                          const float* __restrict__ uo, const float* __restrict__ uc){
    int idx = blockIdx.x*blockDim.x + threadIdx.x;
    if (idx >= Hh*NG) return;
    int k = idx >> 12, c = idx & (NG-1);
    int g = c & 3, hh = c >> 2;
    int cb = hh>>8, bbp = hh&255, rb = k>>8, aa = k&255;
    const float* u = (g==0)?uf:(g==1)?ui:(g==2)?uo:uc;
    int m = rb*4+cb;
    float v = c_SG[m]*u[((size_t)c_CM[m]*256+aa)*256+bbp];
    __half hi = __float2half_rn(v);
    d_Uf16hi[idx] = hi;
    d_Uf16lo[idx] = __float2half_rn(v - __half2float(hi));
}
__global__ void k_build_wout(const float* __restrict__ Wo){
    int idx = blockIdx.x*blockDim.x + threadIdx.x;
    if (idx >= Hh*NOP) return;
    int k = idx / NOP, n = idx % NOP;
    float v = (n < OUTF) ? Wo[(size_t)k*OUTF + n] : 0.f;
    __half hi = __float2half_rn(v);
    d_Wo16hi[idx] = hi;
    d_Wo16lo[idx] = __float2half_rn(v - __half2float(hi));
}
__global__ void k_build_misc(const float* __restrict__ bf, const float* __restrict__ bi,
                             const float* __restrict__ bo, const float* __restrict__ bc){
    int idx = blockIdx.x*blockDim.x + threadIdx.x;
    if (idx == 0) g_bar = 0u;
    if (idx < NG){
        int g = idx & 3, hh = idx >> 2;
        const float* b = (g==0)?bf:(g==1)?bi:(g==2)?bo:bc;
        d_Bcat[idx] = b[hh];
    }
}

// ---- HMMA input GEMM (bf16, 3-product); SINGLE buffer -> 2 blocks/SM ----
#define IA_STR 144
#define IB_STR 272
#define IA_SZ  (128*IA_STR)
#define IB_SZ  (64*IB_STR)
#define IBUF   (2*IA_SZ + 2*IB_SZ)
#define ISMEM  IBUF

__device__ __forceinline__ void gi_load(char* buf, int row0, int col0, int kc, int tid){
    const __nv_bfloat16* Ac[2] = {d_Xhi, d_Xlo};
    const __nv_bfloat16* Bc[2] = {d_Wbhi, d_Wblo};
#pragma unroll
    for (int j = 0; j < 8; j++){
        int i = tid + j*256;
        int comp = i >> 10, rem = i & 1023, r = rem >> 3, s = rem & 7;
        const char* src = (const char*)(Ac[comp] + (size_t)(row0 + r)*Ff + kc*64 + s*8);
        CPA16(smem_u32(buf + comp*IA_SZ + r*IA_STR + s*16), src);
    }
    char* bbuf = buf + 2*IA_SZ;
#pragma unroll
    for (int j = 0; j < 8; j++){
        int i = tid + j*256;
        int comp = i >> 10, rem = i & 1023, r = rem >> 4, s = rem & 15;
        const char* src = (const char*)(Bc[comp] + (size_t)(kc*64 + r)*NG + col0 + s*8);
        CPA16(smem_u32(bbuf + comp*IB_SZ + r*IB_STR + s*16), src);
    }
    CPA_COMMIT();
}

__global__ __launch_bounds__(256,2) void k_gemm_in_mma(){
    extern __shared__ char sm[];
    const int tid = threadIdx.x, lane = tid&31, w = tid>>5;
    const int wm = w&3, wn = w>>2;
    const int col0 = blockIdx.x*128, row0 = blockIdx.y*128;
    float acc[2][8][4];
#pragma unroll
    for (int mi=0;mi<2;mi++)
#pragma unroll
        for (int nj=0;nj<8;nj++)
#pragma unroll
            for (int q=0;q<4;q++) acc[mi][nj][q]=0.f;

    for (int kc = 0; kc < 8; kc++){
        gi_load(sm, row0, col0, kc, tid);
        CPA_WAIT0();
        __syncthreads();
        char* abuf = sm;
        char* bbuf = sm + 2*IA_SZ;
#pragma unroll
        for (int ks = 0; ks < 4; ks++){
            uint32_t ah[2][4], al[2][4], bh[4][4], bl[4][4];
#pragma unroll
            for (int mi = 0; mi < 2; mi++){
                uint32_t aoff = (wm*32 + mi*16 + (lane&15))*IA_STR + ks*32 + (lane>>4)*16;
                LDSM4(ah[mi], smem_u32(abuf + aoff));
                LDSM4(al[mi], smem_u32(abuf + IA_SZ + aoff));
            }
#pragma unroll
            for (int ni = 0; ni < 4; ni++){
                uint32_t boff = (ks*16 + (lane&15))*IB_STR + wn*128 + ni*32 + (lane>>4)*16;
                LDSM4T(bh[ni], smem_u32(bbuf + boff));
                LDSM4T(bl[ni], smem_u32(bbuf + IB_SZ + boff));
            }
#pragma unroll
            for (int mi = 0; mi < 2; mi++)
#pragma unroll
                for (int ni = 0; ni < 4; ni++){
                    MMABF16(acc[mi][2*ni],   ah[mi], bh[ni][0], bh[ni][1]);
                    MMABF16(acc[mi][2*ni],   ah[mi], bl[ni][0], bl[ni][1]);
                    MMABF16(acc[mi][2*ni],   al[mi], bh[ni][0], bh[ni][1]);
                    MMABF16(acc[mi][2*ni+1], ah[mi], bh[ni][2], bh[ni][3]);
                    MMABF16(acc[mi][2*ni+1], ah[mi], bl[ni][2], bl[ni][3]);
                    MMABF16(acc[mi][2*ni+1], al[mi], bh[ni][2], bh[ni][3]);
                }
        }
        __syncthreads();
    }
#pragma unroll
    for (int mi = 0; mi < 2; mi++){
        int r = wm*32 + mi*16 + (lane>>2);
#pragma unroll
        for (int nj = 0; nj < 8; nj++){
            int c = col0 + wn*64 + nj*8 + (lane&3)*2;
            float2 bc = *(const float2*)&d_Bcat[c];
            size_t g0 = (size_t)(row0 + r)*NG + c;
            *(float2*)&d_G[g0] = make_float2(acc[mi][nj][0] + bc.x, acc[mi][nj][1] + bc.y);
            *(float2*)&d_G[g0 + 8*NG] = make_float2(acc[mi][nj][2] + bc.x, acc[mi][nj][3] + bc.y);
        }
    }
}

// ---- HMMA output GEMM (fp16: A = Hall16 single, B = Wo16 hi/lo, 2 products) ----
#define OA_SZ  (128*IA_STR)
#define OBUF   (OA_SZ + 2*IB_SZ)
#define OSMEM  (2*OBUF)

__device__ __forceinline__ void go_load(char* buf, int row0, int col0, int kc, int tid){
#pragma unroll
    for (int j = 0; j < 4; j++){
        int i = tid + j*256;
        int r = i >> 3, s = i & 7;
        const char* src = (const char*)(d_Hall16 + (size_t)(row0 + r)*Hh + kc*64 + s*8);
        CPA16(smem_u32(buf + r*IA_STR + s*16), src);
    }
    char* bbuf = buf + OA_SZ;
    const __half* Bc[2] = {d_Wo16hi, d_Wo16lo};
#pragma unroll
    for (int j = 0; j < 8; j++){
        int i = tid + j*256;
        int comp = i >> 10, rem = i & 1023, r = rem >> 4, s = rem & 15;
        const char* src = (const char*)(Bc[comp] + (size_t)(kc*64 + r)*NOP + col0 + s*8);
        CPA16(smem_u32(bbuf + comp*IB_SZ + r*IB_STR + s*16), src);
    }
    CPA_COMMIT();
}

__global__ __launch_bounds__(256,2) void k_gemm_out_mma(const float* __restrict__ bout,
                                                        float* __restrict__ Out){
    extern __shared__ char sm[];
    const int tid = threadIdx.x, lane = tid&31, w = tid>>5;
    const int wm = w&3, wn = w>>2;
    const int col0 = blockIdx.x*128, row0 = blockIdx.y*128;
    float acc[2][8][4];
#pragma unroll
    for (int mi=0;mi<2;mi++)
#pragma unroll
        for (int nj=0;nj<8;nj++)
#pragma unroll
            for (int q=0;q<4;q++) acc[mi][nj][q]=0.f;

    go_load(sm, row0, col0, 0, tid);
    for (int kc = 0; kc < 16; kc++){
        if (kc < 15) go_load(sm + ((kc+1)&1)*OBUF, row0, col0, kc+1, tid);
        if (kc < 15) CPA_WAIT1(); else CPA_WAIT0();
        __syncthreads();
        char* abuf = sm + (kc&1)*OBUF;
        char* bbuf = abuf + OA_SZ;
#pragma unroll
        for (int ks = 0; ks < 4; ks++){
            uint32_t ah[2][4], bh[4][4], bl[4][4];
#pragma unroll
            for (int mi = 0; mi < 2; mi++){
                uint32_t aoff = (wm*32 + mi*16 + (lane&15))*IA_STR + ks*32 + (lane>>4)*16;
                LDSM4(ah[mi], smem_u32(abuf + aoff));
            }
#pragma unroll
            for (int ni = 0; ni < 4; ni++){
                uint32_t boff = (ks*16 + (lane&15))*IB_STR + wn*128 + ni*32 + (lane>>4)*16;
                LDSM4T(bh[ni], smem_u32(bbuf + boff));
                LDSM4T(bl[ni], smem_u32(bbuf + IB_SZ + boff));
            }
#pragma unroll
            for (int mi = 0; mi < 2; mi++)
#pragma unroll
                for (int ni = 0; ni < 4; ni++){
                    MMAF16(acc[mi][2*ni],   ah[mi], bh[ni][0], bh[ni][1]);
                    MMAF16(acc[mi][2*ni],   ah[mi], bl[ni][0], bl[ni][1]);
                    MMAF16(acc[mi][2*ni+1], ah[mi], bh[ni][2], bh[ni][3]);
                    MMAF16(acc[mi][2*ni+1], ah[mi], bl[ni][2], bl[ni][3]);
                }
        }
        __syncthreads();
    }
    // scalar stores: OUTF=513 is odd, rows only 4B-aligned
#pragma unroll
    for (int mi = 0; mi < 2; mi++){
        int r = wm*32 + mi*16 + (lane>>2);
#pragma unroll
        for (int nj = 0; nj < 8; nj++){
            int c = col0 + wn*64 + nj*8 + (lane&3)*2;
#pragma unroll
            for (int e = 0; e < 2; e++){
                int cc = c + e;
                if (cc < OUTF){
                    float bc = bout[cc];
                    size_t o0 = (size_t)(row0 + r)*OUTF + cc;
                    Out[o0]          = acc[mi][nj][e]     + bc;
                    Out[o0 + 8*OUTF] = acc[mi][nj][e + 2] + bc;
                }
            }
        }
    }
}

// ---- persistent HMMA recurrence (fp16 h, U hi/lo, 2 products) ----
#define OFF_ULO  81920
#define OFF_HS   163840
#define HS_BUF   9216
#define OFF_EX   182272
#define RSMEM    (182272 + 8448)

// release/acquire grid barrier (CG grid.sync pattern; no full membar)
__device__ __forceinline__ void grid_bar(unsigned target){
    __syncthreads();
    if (threadIdx.x == 0){
        asm volatile("red.release.gpu.add.u32 [%0], 1;" :: "l"(&g_bar) : "memory");
        unsigned v;
        do {
            asm volatile("ld.acquire.gpu.u32 %0, [%1];" : "=r"(v) : "l"(&g_bar) : "memory");
        } while (v < target);
    }
    __syncthreads();
}

__global__ __launch_bounds__(256,1) void k_recur_mma(){
    extern __shared__ char sm[];
    const int tid = threadIdx.x, lane = tid&31, w = tid>>5;
    const int blk = blockIdx.x;
    const int c0 = blk*32, u0 = blk*8;
    const int wm = w&3, wn = w>>2;
    char* UHI = sm;
    char* ULO = sm + OFF_ULO;
    char* HSB = sm + OFF_HS;
    float* exch = (float*)(sm + OFF_EX);

    for (int i = tid; i < 1024*4; i += 256){
        int k = i>>2, s = i&3;
        *(uint4*)(UHI + k*80 + s*16) =
            *(const uint4*)((const char*)(d_Uf16hi + (size_t)k*NG + c0) + s*16);
        *(uint4*)(ULO + k*80 + s*16) =
            *(const uint4*)((const char*)(d_Uf16lo + (size_t)k*NG + c0) + s*16);
    }

    float cst[2] = {0.f, 0.f};
    const int pb = tid>>2;
    const int pu = (tid&3)*2;

    for (int t = 0; t < Tt; t++){
        // prefetch G[t] early — latency hides under this step's GEMM.
        // Visibility of h[t-1] is guaranteed by the bottom barrier of step t-1.
        const float* gp = &d_G[((size_t)t*Bb + pb)*NG + c0 + 4*pu];
        float4 g0 = __ldcg((const float4*)gp);
        float4 g1 = __ldcg((const float4*)(gp + 4));

        if (t > 0){
            const char* hsrc = (const char*)(d_Hall16 + ((size_t)(t-1)*Bb << 10));
#pragma unroll
            for (int j = 0; j < 2; j++){
                int i = tid + j*256; int r = i>>3, s = i&7;
                uint4 v = __ldcg((const uint4*)(hsrc + r*2048 + s*16));
                *(uint4*)(HSB + r*144 + s*16) = v;
            }
            __syncthreads();

            float accP[2][4], accQ[2][4];
#pragma unroll
            for (int p=0;p<2;p++)
#pragma unroll
                for (int q=0;q<4;q++){ accP[p][q]=0.f; accQ[p][q]=0.f; }

            for (int kc = 0; kc < 16; kc++){
                uint4 pre[2];
                if (kc < 15){
#pragma unroll
                    for (int j = 0; j < 2; j++){
                        int i = tid + j*256; int r = i>>3, s = i&7;
                        pre[j] = __ldcg((const uint4*)(hsrc + r*2048 + (kc+1)*128 + s*16));
                    }
                }
                char* hs = HSB + (kc&1)*HS_BUF;
#pragma unroll
                for (int ks = 0; ks < 4; ks++){
                    uint32_t ah[4], bh[4], bl[4];
                    uint32_t aoff = (wm*16 + (lane&15))*144 + ks*32 + (lane>>4)*16;
                    LDSM4(ah, smem_u32(hs + aoff));
                    uint32_t brow = kc*64 + ks*16 + (lane&15);
                    uint32_t boff = brow*80 + wn*32 + (lane>>4)*16;
                    LDSM4T(bh, smem_u32(UHI + boff));
                    LDSM4T(bl, smem_u32(ULO + boff));
                    MMAF16(accP[0], ah, bh[0], bh[1]);
                    MMAF16(accP[1], ah, bh[2], bh[3]);
                    MMAF16(accQ[0], ah, bl[0], bl[1]);
                    MMAF16(accQ[1], ah, bl[2], bl[3]);
                }
                if (kc < 15){
                    char* nb = HSB + ((kc+1)&1)*HS_BUF;
#pragma unroll
                    for (int j = 0; j < 2; j++){
                        int i = tid + j*256; int r = i>>3, s = i&7;
                        *(uint4*)(nb + r*144 + s*16) = pre[j];
                    }
                    __syncthreads();
                }
            }
            {
                int r0 = wm*16 + (lane>>2);
                int cb = wn*16 + (lane&3)*2;
                float s0[4], s1[4];
#pragma unroll
                for (int q=0;q<4;q++){
                    s0[q] = accP[0][q] + accQ[0][q];
                    s1[q] = accP[1][q] + accQ[1][q];
                }
                exch[r0*33 + cb]       = s0[0];
                exch[r0*33 + cb + 1]   = s0[1];
                exch[(r0+8)*33 + cb]   = s0[2];
                exch[(r0+8)*33 + cb+1] = s0[3];
                exch[r0*33 + cb + 8]       = s1[0];
                exch[r0*33 + cb + 9]       = s1[1];
                exch[(r0+8)*33 + cb + 8]   = s1[2];
                exch[(r0+8)*33 + cb + 9]   = s1[3];
            }
            __syncthreads();
        }

#pragma unroll
        for (int j = 0; j < 2; j++){
            int u = pu + j;
            float4 g = (j == 0) ? g0 : g1;
            float zf = g.x, zi = g.y, zo = g.z, za = g.w;
            if (t > 0){
                zf += exch[pb*33 + 4*u];
                zi += exch[pb*33 + 4*u + 1];
                zo += exch[pb*33 + 4*u + 2];
                za += exch[pb*33 + 4*u + 3];
            }
            float f  = 1.f/(1.f+expf(-zf));
            float i2 = 1.f/(1.f+expf(-zi));
            float o  = 1.f/(1.f+expf(-zo));
            float cc = i2*tanhf(za) + f*cst[j];
            cst[j] = cc;
            float hv = o*tanhf(cc);
            d_Hall16[((size_t)t*Bb + pb)*Hh + u0 + u] = __float2half_rn(hv);
        }
        // ONE barrier per step; target matches cumulative call count.
        grid_bar((unsigned)(t + 1) * NBLK);
    }
}

// ---- launch ----
extern "C" void kernel_launch(void* const* d_in, const int* in_sizes, int n_in,
                              void* d_out, int out_size){
    (void)in_sizes; (void)n_in; (void)out_size;
    const float* x     = (const float*)d_in[0];
    const float* wfx_w = (const float*)d_in[1];
    const float* wfx_b = (const float*)d_in[2];
    const float* wix_w = (const float*)d_in[3];
    const float* wix_b = (const float*)d_in[4];
    const float* wox_w = (const float*)d_in[5];
    const float* wox_b = (const float*)d_in[6];
    const float* wcx_w = (const float*)d_in[7];
    const float* wcx_b = (const float*)d_in[8];
    const float* ufh_w = (const float*)d_in[9];
    const float* uih_w = (const float*)d_in[10];
    const float* uoh_w = (const float*)d_in[11];
    const float* uch_w = (const float*)d_in[12];
    const float* fco_w = (const float*)d_in[13];
    const float* fco_b = (const float*)d_in[14];
    float* out = (float*)d_out;

    cudaFuncSetAttribute(k_recur_mma, cudaFuncAttributeMaxDynamicSharedMemorySize, RSMEM);
    cudaFuncSetAttribute(k_gemm_in_mma, cudaFuncAttributeMaxDynamicSharedMemorySize, ISMEM);
    cudaFuncSetAttribute(k_gemm_out_mma, cudaFuncAttributeMaxDynamicSharedMemorySize, OSMEM);

    k_build_wbf<<<(Ff*NG + 255)/256, 256>>>(wfx_w, wix_w, wox_w, wcx_w);
    k_split_x<<<(TBm*Ff + 255)/256, 256>>>(x);
    k_build_u<<<(Hh*NG + 255)/256, 256>>>(ufh_w, uih_w, uoh_w, uch_w);
    k_build_wout<<<(Hh*NOP + 255)/256, 256>>>(fco_w);
    k_build_misc<<<(NG + 255)/256, 256>>>(wfx_b, wix_b, wox_b, wcx_b);

    k_gemm_in_mma<<<dim3(NG/128, TBm/128), 256, ISMEM>>>();

    k_recur_mma<<<NBLK, 256, RSMEM>>>();

    k_gemm_out_mma<<<dim3(NOP/128, TBm/128), 256, OSMEM>>>(fco_b, out);
}

// round 14
// speedup vs baseline: 1.5782x; 1.0772x over previous
#include <cuda_runtime.h>
#include <cuda_bf16.h>
#include <cuda_fp16.h>
#include <cstdint>
#include <math.h>

#define Tt 128
#define Bb 64
#define Ff 512
#define Hh 1024
#define NG 4096
#define TBm 8192
#define OUTF 513
#define NOP 640
#define NBLK 128

static __device__ float d_Bcat[NG];
static __device__ float d_G[(size_t)TBm*NG];
static __device__ __half d_W16hi[(size_t)Ff*NG];
static __device__ __half d_W16lo[(size_t)Ff*NG];
static __device__ __half d_X16[(size_t)TBm*Ff];
static __device__ __half d_Uf16hi[(size_t)Hh*NG];
static __device__ __half d_Uf16lo[(size_t)Hh*NG];
static __device__ __half d_Hall16[(size_t)TBm*Hh];
static __device__ __half d_Wo16hi[(size_t)Hh*NOP];
static __device__ __half d_Wo16lo[(size_t)Hh*NOP];
static __device__ unsigned g_bar;

__constant__ int   c_CM[16] = {0,1,2,3, 1,0,3,2, 2,3,0,1, 3,2,1,0};
__constant__ float c_SG[16] = {1,1,1,1, -1,1,1,-1, -1,-1,1,1, -1,1,-1,1};

// ---- PTX helpers (sm_80-baseline, valid on sm_103) ----
__device__ __forceinline__ uint32_t smem_u32(const void* p){
    uint32_t a; asm("{ .reg .u64 t; cvta.to.shared.u64 t, %1; cvt.u32.u64 %0, t; }":"=r"(a):"l"(p)); return a;
}
#define LDSM4(r,a) asm volatile("ldmatrix.sync.aligned.m8n8.x4.shared.b16 {%0,%1,%2,%3}, [%4];" \
    :"=r"((r)[0]),"=r"((r)[1]),"=r"((r)[2]),"=r"((r)[3]):"r"(a))
#define LDSM4T(r,a) asm volatile("ldmatrix.sync.aligned.m8n8.x4.trans.shared.b16 {%0,%1,%2,%3}, [%4];" \
    :"=r"((r)[0]),"=r"((r)[1]),"=r"((r)[2]),"=r"((r)[3]):"r"(a))
#define MMAF16(c,a,b0,b1) asm volatile( \
    "mma.sync.aligned.m16n8k16.row.col.f32.f16.f16.f32 {%0,%1,%2,%3},{%4,%5,%6,%7},{%8,%9},{%0,%1,%2,%3};" \
    :"+f"((c)[0]),"+f"((c)[1]),"+f"((c)[2]),"+f"((c)[3]) \
    :"r"((a)[0]),"r"((a)[1]),"r"((a)[2]),"r"((a)[3]),"r"(b0),"r"(b1))
#define CPA16(dst,src) asm volatile("cp.async.cg.shared.global [%0], [%1], 16;"::"r"(dst),"l"(src))
#define CPA_COMMIT()   asm volatile("cp.async.commit_group;":::"memory")
#define CPA_WAIT1()    asm volatile("cp.async.wait_group 1;":::"memory")
#define CPA_WAIT0()    asm volatile("cp.async.wait_group 0;":::"memory")

__device__ __forceinline__ float fsig(float x){ return 1.f/(1.f + __expf(-x)); }

// ---- builds (gate-interleaved cols: col = 4h + g) ----
__global__ void k_build_w16(const float* __restrict__ wf, const float* __restrict__ wi,
                            const float* __restrict__ wo, const float* __restrict__ wc){
    int idx = blockIdx.x*blockDim.x + threadIdx.x;
    if (idx >= Ff*NG) return;
    int k = idx >> 12, c = idx & (NG-1);
    int g = c & 3, hh = c >> 2;
    int cb = hh>>8, bbp = hh&255, rb = k>>7, aa = k&127;
    const float* w = (g==0)?wf:(g==1)?wi:(g==2)?wo:wc;
    int m = rb*4+cb;
    float v = c_SG[m]*w[((size_t)c_CM[m]*128+aa)*256+bbp];
    __half hi = __float2half_rn(v);
    d_W16hi[idx] = hi;
    d_W16lo[idx] = __float2half_rn(v - __half2float(hi));
}
__global__ void k_split_x(const float* __restrict__ x){
    int idx = blockIdx.x*blockDim.x + threadIdx.x;
    if (idx >= TBm*Ff) return;
    d_X16[idx] = __float2half_rn(x[idx]);
}
__global__ void k_build_u(const float* __restrict__ uf, const float* __restrict__ ui,
                          const float* __restrict__ uo, const float* __restrict__ uc){
    int idx = blockIdx.x*blockDim.x + threadIdx.x;
    if (idx >= Hh*NG) return;
    int k = idx >> 12, c = idx & (NG-1);
    int g = c & 3, hh = c >> 2;
    int cb = hh>>8, bbp = hh&255, rb = k>>8, aa = k&255;
    const float* u = (g==0)?uf:(g==1)?ui:(g==2)?uo:uc;
    int m = rb*4+cb;
    float v = c_SG[m]*u[((size_t)c_CM[m]*256+aa)*256+bbp];
    __half hi = __float2half_rn(v);
    d_Uf16hi[idx] = hi;
    d_Uf16lo[idx] = __float2half_rn(v - __half2float(hi));
}
__global__ void k_build_wout(const float* __restrict__ Wo){
    int idx = blockIdx.x*blockDim.x + threadIdx.x;
    if (idx >= Hh*NOP) return;
    int k = idx / NOP, n = idx % NOP;
    float v = (n < OUTF) ? Wo[(size_t)k*OUTF + n] : 0.f;
    __half hi = __float2half_rn(v);
    d_Wo16hi[idx] = hi;
    d_Wo16lo[idx] = __float2half_rn(v - __half2float(hi));
}
__global__ void k_build_misc(const float* __restrict__ bf, const float* __restrict__ bi,
                             const float* __restrict__ bo, const float* __restrict__ bc){
    int idx = blockIdx.x*blockDim.x + threadIdx.x;
    if (idx == 0) g_bar = 0u;
    if (idx < NG){
        int g = idx & 3, hh = idx >> 2;
        const float* b = (g==0)?bf:(g==1)?bi:(g==2)?bo:bc;
        d_Bcat[idx] = b[hh];
    }
}

// ---- shared tile constants ----
#define IA_STR 144
#define IB_STR 272
#define IA_SZ  (128*IA_STR)
#define IB_SZ  (64*IB_STR)

// ---- HMMA input GEMM (fp16: A=X16 single, B=W16 hi/lo, 2 products); 2 blk/SM ----
#define GIBUF  (IA_SZ + 2*IB_SZ)
#define ISMEM  GIBUF

__device__ __forceinline__ void gi_load(char* buf, int row0, int col0, int kc, int tid){
#pragma unroll
    for (int j = 0; j < 4; j++){
        int i = tid + j*256;
        int r = i >> 3, s = i & 7;
        const char* src = (const char*)(d_X16 + (size_t)(row0 + r)*Ff + kc*64 + s*8);
        CPA16(smem_u32(buf + r*IA_STR + s*16), src);
    }
    char* bbuf = buf + IA_SZ;
    const __half* Bc[2] = {d_W16hi, d_W16lo};
#pragma unroll
    for (int j = 0; j < 8; j++){
        int i = tid + j*256;
        int comp = i >> 10, rem = i & 1023, r = rem >> 4, s = rem & 15;
        const char* src = (const char*)(Bc[comp] + (size_t)(kc*64 + r)*NG + col0 + s*8);
        CPA16(smem_u32(bbuf + comp*IB_SZ + r*IB_STR + s*16), src);
    }
    CPA_COMMIT();
}

__global__ __launch_bounds__(256,2) void k_gemm_in_mma(){
    extern __shared__ char sm[];
    const int tid = threadIdx.x, lane = tid&31, w = tid>>5;
    const int wm = w&3, wn = w>>2;
    const int col0 = blockIdx.x*128, row0 = blockIdx.y*128;
    float acc[2][8][4];
#pragma unroll
    for (int mi=0;mi<2;mi++)
#pragma unroll
        for (int nj=0;nj<8;nj++)
#pragma unroll
            for (int q=0;q<4;q++) acc[mi][nj][q]=0.f;

    for (int kc = 0; kc < 8; kc++){
        gi_load(sm, row0, col0, kc, tid);
        CPA_WAIT0();
        __syncthreads();
        char* abuf = sm;
        char* bbuf = sm + IA_SZ;
#pragma unroll
        for (int ks = 0; ks < 4; ks++){
            uint32_t ah[2][4], bh[4][4], bl[4][4];
#pragma unroll
            for (int mi = 0; mi < 2; mi++){
                uint32_t aoff = (wm*32 + mi*16 + (lane&15))*IA_STR + ks*32 + (lane>>4)*16;
                LDSM4(ah[mi], smem_u32(abuf + aoff));
            }
#pragma unroll
            for (int ni = 0; ni < 4; ni++){
                uint32_t boff = (ks*16 + (lane&15))*IB_STR + wn*128 + ni*32 + (lane>>4)*16;
                LDSM4T(bh[ni], smem_u32(bbuf + boff));
                LDSM4T(bl[ni], smem_u32(bbuf + IB_SZ + boff));
            }
#pragma unroll
            for (int mi = 0; mi < 2; mi++)
#pragma unroll
                for (int ni = 0; ni < 4; ni++){
                    MMAF16(acc[mi][2*ni],   ah[mi], bh[ni][0], bh[ni][1]);
                    MMAF16(acc[mi][2*ni],   ah[mi], bl[ni][0], bl[ni][1]);
                    MMAF16(acc[mi][2*ni+1], ah[mi], bh[ni][2], bh[ni][3]);
                    MMAF16(acc[mi][2*ni+1], ah[mi], bl[ni][2], bl[ni][3]);
                }
        }
        __syncthreads();
    }
#pragma unroll
    for (int mi = 0; mi < 2; mi++){
        int r = wm*32 + mi*16 + (lane>>2);
#pragma unroll
        for (int nj = 0; nj < 8; nj++){
            int c = col0 + wn*64 + nj*8 + (lane&3)*2;
            float2 bc = *(const float2*)&d_Bcat[c];
            size_t g0 = (size_t)(row0 + r)*NG + c;
            *(float2*)&d_G[g0] = make_float2(acc[mi][nj][0] + bc.x, acc[mi][nj][1] + bc.y);
            *(float2*)&d_G[g0 + 8*NG] = make_float2(acc[mi][nj][2] + bc.x, acc[mi][nj][3] + bc.y);
        }
    }
}

// ---- HMMA output GEMM (fp16: A = Hall16 single, B = Wo16 hi/lo) ----
#define OA_SZ  (128*IA_STR)
#define OBUF   (OA_SZ + 2*IB_SZ)
#define OSMEM  (2*OBUF)

__device__ __forceinline__ void go_load(char* buf, int row0, int col0, int kc, int tid){
#pragma unroll
    for (int j = 0; j < 4; j++){
        int i = tid + j*256;
        int r = i >> 3, s = i & 7;
        const char* src = (const char*)(d_Hall16 + (size_t)(row0 + r)*Hh + kc*64 + s*8);
        CPA16(smem_u32(buf + r*IA_STR + s*16), src);
    }
    char* bbuf = buf + OA_SZ;
    const __half* Bc[2] = {d_Wo16hi, d_Wo16lo};
#pragma unroll
    for (int j = 0; j < 8; j++){
        int i = tid + j*256;
        int comp = i >> 10, rem = i & 1023, r = rem >> 4, s = rem & 15;
        const char* src = (const char*)(Bc[comp] + (size_t)(kc*64 + r)*NOP + col0 + s*8);
        CPA16(smem_u32(bbuf + comp*IB_SZ + r*IB_STR + s*16), src);
    }
    CPA_COMMIT();
}

__global__ __launch_bounds__(256,2) void k_gemm_out_mma(const float* __restrict__ bout,
                                                        float* __restrict__ Out){
    extern __shared__ char sm[];
    const int tid = threadIdx.x, lane = tid&31, w = tid>>5;
    const int wm = w&3, wn = w>>2;
    const int col0 = blockIdx.x*128, row0 = blockIdx.y*128;
    float acc[2][8][4];
#pragma unroll
    for (int mi=0;mi<2;mi++)
#pragma unroll
        for (int nj=0;nj<8;nj++)
#pragma unroll
            for (int q=0;q<4;q++) acc[mi][nj][q]=0.f;

    go_load(sm, row0, col0, 0, tid);
    for (int kc = 0; kc < 16; kc++){
        if (kc < 15) go_load(sm + ((kc+1)&1)*OBUF, row0, col0, kc+1, tid);
        if (kc < 15) CPA_WAIT1(); else CPA_WAIT0();
        __syncthreads();
        char* abuf = sm + (kc&1)*OBUF;
        char* bbuf = abuf + OA_SZ;
#pragma unroll
        for (int ks = 0; ks < 4; ks++){
            uint32_t ah[2][4], bh[4][4], bl[4][4];
#pragma unroll
            for (int mi = 0; mi < 2; mi++){
                uint32_t aoff = (wm*32 + mi*16 + (lane&15))*IA_STR + ks*32 + (lane>>4)*16;
                LDSM4(ah[mi], smem_u32(abuf + aoff));
            }
#pragma unroll
            for (int ni = 0; ni < 4; ni++){
                uint32_t boff = (ks*16 + (lane&15))*IB_STR + wn*128 + ni*32 + (lane>>4)*16;
                LDSM4T(bh[ni], smem_u32(bbuf + boff));
                LDSM4T(bl[ni], smem_u32(bbuf + IB_SZ + boff));
            }
#pragma unroll
            for (int mi = 0; mi < 2; mi++)
#pragma unroll
                for (int ni = 0; ni < 4; ni++){
                    MMAF16(acc[mi][2*ni],   ah[mi], bh[ni][0], bh[ni][1]);
                    MMAF16(acc[mi][2*ni],   ah[mi], bl[ni][0], bl[ni][1]);
                    MMAF16(acc[mi][2*ni+1], ah[mi], bh[ni][2], bh[ni][3]);
                    MMAF16(acc[mi][2*ni+1], ah[mi], bl[ni][2], bl[ni][3]);
                }
        }
        __syncthreads();
    }
    // scalar stores: OUTF=513 is odd, rows only 4B-aligned
#pragma unroll
    for (int mi = 0; mi < 2; mi++){
        int r = wm*32 + mi*16 + (lane>>2);
#pragma unroll
        for (int nj = 0; nj < 8; nj++){
            int c = col0 + wn*64 + nj*8 + (lane&3)*2;
#pragma unroll
            for (int e = 0; e < 2; e++){
                int cc = c + e;
                if (cc < OUTF){
                    float bc = bout[cc];
                    size_t o0 = (size_t)(row0 + r)*OUTF + cc;
                    Out[o0]          = acc[mi][nj][e]     + bc;
                    Out[o0 + 8*OUTF] = acc[mi][nj][e + 2] + bc;
                }
            }
        }
    }
}

// ---- persistent HMMA recurrence (fp16 h, U hi/lo, distance-2 prefetch) ----
#define OFF_ULO  81920
#define OFF_HS   163840
#define HS_BUF   9216
#define OFF_EX   182272
#define RSMEM    (182272 + 8448)

__device__ __forceinline__ void grid_bar(unsigned target){
    __syncthreads();
    if (threadIdx.x == 0){
        asm volatile("red.release.gpu.add.u32 [%0], 1;" :: "l"(&g_bar) : "memory");
        unsigned v;
        do {
            asm volatile("ld.acquire.gpu.u32 %0, [%1];" : "=r"(v) : "l"(&g_bar) : "memory");
        } while (v < target);
    }
    __syncthreads();
}

__global__ __launch_bounds__(256,1) void k_recur_mma(){
    extern __shared__ char sm[];
    const int tid = threadIdx.x, lane = tid&31, w = tid>>5;
    const int blk = blockIdx.x;
    const int c0 = blk*32, u0 = blk*8;
    const int wm = w&3, wn = w>>2;
    char* UHI = sm;
    char* ULO = sm + OFF_ULO;
    char* HSB = sm + OFF_HS;
    float* exch = (float*)(sm + OFF_EX);

    for (int i = tid; i < 1024*4; i += 256){
        int k = i>>2, s = i&3;
        *(uint4*)(UHI + k*80 + s*16) =
            *(const uint4*)((const char*)(d_Uf16hi + (size_t)k*NG + c0) + s*16);
        *(uint4*)(ULO + k*80 + s*16) =
            *(const uint4*)((const char*)(d_Uf16lo + (size_t)k*NG + c0) + s*16);
    }

    float cst[2] = {0.f, 0.f};
    const int pb = tid>>2;
    const int pu = (tid&3)*2;
    const int hr = tid>>3, hsh = (tid&7)*16;        // staging coords
    const int hr2 = (tid+256)>>3, hsh2 = ((tid+256)&7)*16;

    for (int t = 0; t < Tt; t++){
        // prefetch G[t] early — latency hides under this step's GEMM
        const float* gp = &d_G[((size_t)t*Bb + pb)*NG + c0 + 4*pu];
        float4 g0 = __ldcg((const float4*)gp);
        float4 g1 = __ldcg((const float4*)(gp + 4));

        if (t > 0){
            const char* hsrc = (const char*)(d_Hall16 + ((size_t)(t-1)*Bb << 10));
            // stage chunk 0 directly; prefetch chunk 1 into regs
            {
                uint4 v0 = __ldcg((const uint4*)(hsrc + hr*2048 + hsh));
                uint4 v1 = __ldcg((const uint4*)(hsrc + hr2*2048 + hsh2));
                *(uint4*)(HSB + hr*144 + hsh) = v0;
                *(uint4*)(HSB + hr2*144 + hsh2) = v1;
            }
            uint4 p1a = __ldcg((const uint4*)(hsrc + hr*2048 + 128 + hsh));
            uint4 p1b = __ldcg((const uint4*)(hsrc + hr2*2048 + 128 + hsh2));
            __syncthreads();

            float accP[2][4], accQ[2][4];
#pragma unroll
            for (int p=0;p<2;p++)
#pragma unroll
                for (int q=0;q<4;q++){ accP[p][q]=0.f; accQ[p][q]=0.f; }

#pragma unroll 2
            for (int kc = 0; kc < 16; kc++){
                uint4 p2a, p2b;
                if (kc < 14){
                    p2a = __ldcg((const uint4*)(hsrc + hr*2048 + (kc+2)*128 + hsh));
                    p2b = __ldcg((const uint4*)(hsrc + hr2*2048 + (kc+2)*128 + hsh2));
                }
                char* hs = HSB + (kc&1)*HS_BUF;
#pragma unroll
                for (int ks = 0; ks < 4; ks++){
                    uint32_t ah[4], bh[4], bl[4];
                    uint32_t aoff = (wm*16 + (lane&15))*144 + ks*32 + (lane>>4)*16;
                    LDSM4(ah, smem_u32(hs + aoff));
                    uint32_t brow = kc*64 + ks*16 + (lane&15);
                    uint32_t boff = brow*80 + wn*32 + (lane>>4)*16;
                    LDSM4T(bh, smem_u32(UHI + boff));
                    LDSM4T(bl, smem_u32(ULO + boff));
                    MMAF16(accP[0], ah, bh[0], bh[1]);
                    MMAF16(accP[1], ah, bh[2], bh[3]);
                    MMAF16(accQ[0], ah, bl[0], bl[1]);
                    MMAF16(accQ[1], ah, bl[2], bl[3]);
                }
                if (kc < 15){
                    char* nb = HSB + ((kc+1)&1)*HS_BUF;
                    *(uint4*)(nb + hr*144 + hsh) = p1a;
                    *(uint4*)(nb + hr2*144 + hsh2) = p1b;
                    __syncthreads();
                    p1a = p2a; p1b = p2b;
                }
            }
            {
                int r0 = wm*16 + (lane>>2);
                int cb = wn*16 + (lane&3)*2;
                float s0[4], s1[4];
#pragma unroll
                for (int q=0;q<4;q++){
                    s0[q] = accP[0][q] + accQ[0][q];
                    s1[q] = accP[1][q] + accQ[1][q];
                }
                exch[r0*33 + cb]       = s0[0];
                exch[r0*33 + cb + 1]   = s0[1];
                exch[(r0+8)*33 + cb]   = s0[2];
                exch[(r0+8)*33 + cb+1] = s0[3];
                exch[r0*33 + cb + 8]       = s1[0];
                exch[r0*33 + cb + 9]       = s1[1];
                exch[(r0+8)*33 + cb + 8]   = s1[2];
                exch[(r0+8)*33 + cb + 9]   = s1[3];
            }
            __syncthreads();
        }

#pragma unroll
        for (int j = 0; j < 2; j++){
            int u = pu + j;
            float4 g = (j == 0) ? g0 : g1;
            float zf = g.x, zi = g.y, zo = g.z, za = g.w;
            if (t > 0){
                zf += exch[pb*33 + 4*u];
                zi += exch[pb*33 + 4*u + 1];
                zo += exch[pb*33 + 4*u + 2];
                za += exch[pb*33 + 4*u + 3];
            }
            float f  = fsig(zf);
            float i2 = fsig(zi);
            float o  = fsig(zo);
            float cc = i2*tanhf(za) + f*cst[j];
            cst[j] = cc;
            float hv = o*tanhf(cc);
            d_Hall16[((size_t)t*Bb + pb)*Hh + u0 + u] = __float2half_rn(hv);
        }
        grid_bar((unsigned)(t + 1) * NBLK);
    }
}

// ---- launch ----
extern "C" void kernel_launch(void* const* d_in, const int* in_sizes, int n_in,
                              void* d_out, int out_size){
    (void)in_sizes; (void)n_in; (void)out_size;
    const float* x     = (const float*)d_in[0];
    const float* wfx_w = (const float*)d_in[1];
    const float* wfx_b = (const float*)d_in[2];
    const float* wix_w = (const float*)d_in[3];
    const float* wix_b = (const float*)d_in[4];
    const float* wox_w = (const float*)d_in[5];
    const float* wox_b = (const float*)d_in[6];
    const float* wcx_w = (const float*)d_in[7];
    const float* wcx_b = (const float*)d_in[8];
    const float* ufh_w = (const float*)d_in[9];
    const float* uih_w = (const float*)d_in[10];
    const float* uoh_w = (const float*)d_in[11];
    const float* uch_w = (const float*)d_in[12];
    const float* fco_w = (const float*)d_in[13];
    const float* fco_b = (const float*)d_in[14];
    float* out = (float*)d_out;

    cudaFuncSetAttribute(k_recur_mma, cudaFuncAttributeMaxDynamicSharedMemorySize, RSMEM);
    cudaFuncSetAttribute(k_gemm_in_mma, cudaFuncAttributeMaxDynamicSharedMemorySize, ISMEM);
    cudaFuncSetAttribute(k_gemm_out_mma, cudaFuncAttributeMaxDynamicSharedMemorySize, OSMEM);

    k_build_w16<<<(Ff*NG + 255)/256, 256>>>(wfx_w, wix_w, wox_w, wcx_w);
    k_split_x<<<(TBm*Ff + 255)/256, 256>>>(x);
    k_build_u<<<(Hh*NG + 255)/256, 256>>>(ufh_w, uih_w, uoh_w, uch_w);
    k_build_wout<<<(Hh*NOP + 255)/256, 256>>>(fco_w);
    k_build_misc<<<(NG + 255)/256, 256>>>(wfx_b, wix_b, wox_b, wcx_b);

    k_gemm_in_mma<<<dim3(NG/128, TBm/128), 256, ISMEM>>>();

    k_recur_mma<<<NBLK, 256, RSMEM>>>();

    k_gemm_out_mma<<<dim3(NOP/128, TBm/128), 256, OSMEM>>>(fco_b, out);
}

// round 15
// speedup vs baseline: 1.6103x; 1.0203x over previous
#include <cuda_runtime.h>
#include <cuda_bf16.h>
#include <cuda_fp16.h>
#include <cstdint>
#include <math.h>

#define Tt 128
#define Bb 64
#define Ff 512
#define Hh 1024
#define NG 4096
#define TBm 8192
#define OUTF 513
#define NOP 640
#define NBLK 128

static __device__ float d_Bcat[NG];
static __device__ float d_G[(size_t)TBm*NG];
static __device__ __half d_W16hi[(size_t)Ff*NG];
static __device__ __half d_W16lo[(size_t)Ff*NG];
static __device__ __half d_X16[(size_t)TBm*Ff];
static __device__ __half d_Uf16[(size_t)Hh*NG];
static __device__ __half d_Hall16[(size_t)TBm*Hh];
static __device__ __half d_Wo16hi[(size_t)Hh*NOP];
static __device__ __half d_Wo16lo[(size_t)Hh*NOP];
static __device__ unsigned g_bar;

__constant__ int   c_CM[16] = {0,1,2,3, 1,0,3,2, 2,3,0,1, 3,2,1,0};
__constant__ float c_SG[16] = {1,1,1,1, -1,1,1,-1, -1,-1,1,1, -1,1,-1,1};

// ---- PTX helpers (sm_80-baseline, valid on sm_103) ----
__device__ __forceinline__ uint32_t smem_u32(const void* p){
    uint32_t a; asm("{ .reg .u64 t; cvta.to.shared.u64 t, %1; cvt.u32.u64 %0, t; }":"=r"(a):"l"(p)); return a;
}
#define LDSM4(r,a) asm volatile("ldmatrix.sync.aligned.m8n8.x4.shared.b16 {%0,%1,%2,%3}, [%4];" \
    :"=r"((r)[0]),"=r"((r)[1]),"=r"((r)[2]),"=r"((r)[3]):"r"(a))
#define LDSM4T(r,a) asm volatile("ldmatrix.sync.aligned.m8n8.x4.trans.shared.b16 {%0,%1,%2,%3}, [%4];" \
    :"=r"((r)[0]),"=r"((r)[1]),"=r"((r)[2]),"=r"((r)[3]):"r"(a))
#define MMAF16(c,a,b0,b1) asm volatile( \
    "mma.sync.aligned.m16n8k16.row.col.f32.f16.f16.f32 {%0,%1,%2,%3},{%4,%5,%6,%7},{%8,%9},{%0,%1,%2,%3};" \
    :"+f"((c)[0]),"+f"((c)[1]),"+f"((c)[2]),"+f"((c)[3]) \
    :"r"((a)[0]),"r"((a)[1]),"r"((a)[2]),"r"((a)[3]),"r"(b0),"r"(b1))
#define CPA16(dst,src) asm volatile("cp.async.cg.shared.global [%0], [%1], 16;"::"r"(dst),"l"(src))
#define CPA_COMMIT()   asm volatile("cp.async.commit_group;":::"memory")
#define CPA_WAIT1()    asm volatile("cp.async.wait_group 1;":::"memory")
#define CPA_WAIT0()    asm volatile("cp.async.wait_group 0;":::"memory")

__device__ __forceinline__ float fsig(float x){ return 1.f/(1.f + __expf(-x)); }

// ---- builds (gate-interleaved cols: col = 4h + g) ----
__global__ void k_build_w16(const float* __restrict__ wf, const float* __restrict__ wi,
                            const float* __restrict__ wo, const float* __restrict__ wc){
    int idx = blockIdx.x*blockDim.x + threadIdx.x;
    if (idx >= Ff*NG) return;
    int k = idx >> 12, c = idx & (NG-1);
    int g = c & 3, hh = c >> 2;
    int cb = hh>>8, bbp = hh&255, rb = k>>7, aa = k&127;
    const float* w = (g==0)?wf:(g==1)?wi:(g==2)?wo:wc;
    int m = rb*4+cb;
    float v = c_SG[m]*w[((size_t)c_CM[m]*128+aa)*256+bbp];
    __half hi = __float2half_rn(v);
    d_W16hi[idx] = hi;
    d_W16lo[idx] = __float2half_rn(v - __half2float(hi));
}
__global__ void k_split_x(const float* __restrict__ x){
    int idx = blockIdx.x*blockDim.x + threadIdx.x;
    if (idx >= TBm*Ff) return;
    d_X16[idx] = __float2half_rn(x[idx]);
}
__global__ void k_build_u(const float* __restrict__ uf, const float* __restrict__ ui,
                          const float* __restrict__ uo, const float* __restrict__ uc){
    int idx = blockIdx.x*blockDim.x + threadIdx.x;
    if (idx >= Hh*NG) return;
    int k = idx >> 12, c = idx & (NG-1);
    int g = c & 3, hh = c >> 2;
    int cb = hh>>8, bbp = hh&255, rb = k>>8, aa = k&255;
    const float* u = (g==0)?uf:(g==1)?ui:(g==2)?uo:uc;
    int m = rb*4+cb;
    float v = c_SG[m]*u[((size_t)c_CM[m]*256+aa)*256+bbp];
    d_Uf16[idx] = __float2half_rn(v);
}
__global__ void k_build_wout(const float* __restrict__ Wo){
    int idx = blockIdx.x*blockDim.x + threadIdx.x;
    if (idx >= Hh*NOP) return;
    int k = idx / NOP, n = idx % NOP;
    float v = (n < OUTF) ? Wo[(size_t)k*OUTF + n] : 0.f;
    __half hi = __float2half_rn(v);
    d_Wo16hi[idx] = hi;
    d_Wo16lo[idx] = __float2half_rn(v - __half2float(hi));
}
__global__ void k_build_misc(const float* __restrict__ bf, const float* __restrict__ bi,
                             const float* __restrict__ bo, const float* __restrict__ bc){
    int idx = blockIdx.x*blockDim.x + threadIdx.x;
    if (idx == 0) g_bar = 0u;
    if (idx < NG){
        int g = idx & 3, hh = idx >> 2;
        const float* b = (g==0)?bf:(g==1)?bi:(g==2)?bo:bc;
        d_Bcat[idx] = b[hh];
    }
}

// ---- shared tile constants ----
#define IA_STR 144
#define IB_STR 272
#define IA_SZ  (128*IA_STR)
#define IB_SZ  (64*IB_STR)

// ---- HMMA input GEMM (fp16: A=X16 single, B=W16 hi/lo, 2 products); 2 blk/SM ----
#define GIBUF  (IA_SZ + 2*IB_SZ)
#define ISMEM  GIBUF

__device__ __forceinline__ void gi_load(char* buf, int row0, int col0, int kc, int tid){
#pragma unroll
    for (int j = 0; j < 4; j++){
        int i = tid + j*256;
        int r = i >> 3, s = i & 7;
        const char* src = (const char*)(d_X16 + (size_t)(row0 + r)*Ff + kc*64 + s*8);
        CPA16(smem_u32(buf + r*IA_STR + s*16), src);
    }
    char* bbuf = buf + IA_SZ;
    const __half* Bc[2] = {d_W16hi, d_W16lo};
#pragma unroll
    for (int j = 0; j < 8; j++){
        int i = tid + j*256;
        int comp = i >> 10, rem = i & 1023, r = rem >> 4, s = rem & 15;
        const char* src = (const char*)(Bc[comp] + (size_t)(kc*64 + r)*NG + col0 + s*8);
        CPA16(smem_u32(bbuf + comp*IB_SZ + r*IB_STR + s*16), src);
    }
    CPA_COMMIT();
}

__global__ __launch_bounds__(256,2) void k_gemm_in_mma(){
    extern __shared__ char sm[];
    const int tid = threadIdx.x, lane = tid&31, w = tid>>5;
    const int wm = w&3, wn = w>>2;
    const int col0 = blockIdx.x*128, row0 = blockIdx.y*128;
    float acc[2][8][4];
#pragma unroll
    for (int mi=0;mi<2;mi++)
#pragma unroll
        for (int nj=0;nj<8;nj++)
#pragma unroll
            for (int q=0;q<4;q++) acc[mi][nj][q]=0.f;

    for (int kc = 0; kc < 8; kc++){
        gi_load(sm, row0, col0, kc, tid);
        CPA_WAIT0();
        __syncthreads();
        char* abuf = sm;
        char* bbuf = sm + IA_SZ;
#pragma unroll
        for (int ks = 0; ks < 4; ks++){
            uint32_t ah[2][4], bh[4][4], bl[4][4];
#pragma unroll
            for (int mi = 0; mi < 2; mi++){
                uint32_t aoff = (wm*32 + mi*16 + (lane&15))*IA_STR + ks*32 + (lane>>4)*16;
                LDSM4(ah[mi], smem_u32(abuf + aoff));
            }
#pragma unroll
            for (int ni = 0; ni < 4; ni++){
                uint32_t boff = (ks*16 + (lane&15))*IB_STR + wn*128 + ni*32 + (lane>>4)*16;
                LDSM4T(bh[ni], smem_u32(bbuf + boff));
                LDSM4T(bl[ni], smem_u32(bbuf + IB_SZ + boff));
            }
#pragma unroll
            for (int mi = 0; mi < 2; mi++)
#pragma unroll
                for (int ni = 0; ni < 4; ni++){
                    MMAF16(acc[mi][2*ni],   ah[mi], bh[ni][0], bh[ni][1]);
                    MMAF16(acc[mi][2*ni],   ah[mi], bl[ni][0], bl[ni][1]);
                    MMAF16(acc[mi][2*ni+1], ah[mi], bh[ni][2], bh[ni][3]);
                    MMAF16(acc[mi][2*ni+1], ah[mi], bl[ni][2], bl[ni][3]);
                }
        }
        __syncthreads();
    }
#pragma unroll
    for (int mi = 0; mi < 2; mi++){
        int r = wm*32 + mi*16 + (lane>>2);
#pragma unroll
        for (int nj = 0; nj < 8; nj++){
            int c = col0 + wn*64 + nj*8 + (lane&3)*2;
            float2 bc = *(const float2*)&d_Bcat[c];
            size_t g0 = (size_t)(row0 + r)*NG + c;
            *(float2*)&d_G[g0] = make_float2(acc[mi][nj][0] + bc.x, acc[mi][nj][1] + bc.y);
            *(float2*)&d_G[g0 + 8*NG] = make_float2(acc[mi][nj][2] + bc.x, acc[mi][nj][3] + bc.y);
        }
    }
}

// ---- HMMA output GEMM (fp16: A = Hall16 single, B = Wo16 hi/lo) ----
#define OA_SZ  (128*IA_STR)
#define OBUF   (OA_SZ + 2*IB_SZ)
#define OSMEM  (2*OBUF)

__device__ __forceinline__ void go_load(char* buf, int row0, int col0, int kc, int tid){
#pragma unroll
    for (int j = 0; j < 4; j++){
        int i = tid + j*256;
        int r = i >> 3, s = i & 7;
        const char* src = (const char*)(d_Hall16 + (size_t)(row0 + r)*Hh + kc*64 + s*8);
        CPA16(smem_u32(buf + r*IA_STR + s*16), src);
    }
    char* bbuf = buf + OA_SZ;
    const __half* Bc[2] = {d_Wo16hi, d_Wo16lo};
#pragma unroll
    for (int j = 0; j < 8; j++){
        int i = tid + j*256;
        int comp = i >> 10, rem = i & 1023, r = rem >> 4, s = rem & 15;
        const char* src = (const char*)(Bc[comp] + (size_t)(kc*64 + r)*NOP + col0 + s*8);
        CPA16(smem_u32(bbuf + comp*IB_SZ + r*IB_STR + s*16), src);
    }
    CPA_COMMIT();
}

__global__ __launch_bounds__(256,2) void k_gemm_out_mma(const float* __restrict__ bout,
                                                        float* __restrict__ Out){
    extern __shared__ char sm[];
    const int tid = threadIdx.x, lane = tid&31, w = tid>>5;
    const int wm = w&3, wn = w>>2;
    const int col0 = blockIdx.x*128, row0 = blockIdx.y*128;
    float acc[2][8][4];
#pragma unroll
    for (int mi=0;mi<2;mi++)
#pragma unroll
        for (int nj=0;nj<8;nj++)
#pragma unroll
            for (int q=0;q<4;q++) acc[mi][nj][q]=0.f;

    go_load(sm, row0, col0, 0, tid);
    for (int kc = 0; kc < 16; kc++){
        if (kc < 15) go_load(sm + ((kc+1)&1)*OBUF, row0, col0, kc+1, tid);
        if (kc < 15) CPA_WAIT1(); else CPA_WAIT0();
        __syncthreads();
        char* abuf = sm + (kc&1)*OBUF;
        char* bbuf = abuf + OA_SZ;
#pragma unroll
        for (int ks = 0; ks < 4; ks++){
            uint32_t ah[2][4], bh[4][4], bl[4][4];
#pragma unroll
            for (int mi = 0; mi < 2; mi++){
                uint32_t aoff = (wm*32 + mi*16 + (lane&15))*IA_STR + ks*32 + (lane>>4)*16;
                LDSM4(ah[mi], smem_u32(abuf + aoff));
            }
#pragma unroll
            for (int ni = 0; ni < 4; ni++){
                uint32_t boff = (ks*16 + (lane&15))*IB_STR + wn*128 + ni*32 + (lane>>4)*16;
                LDSM4T(bh[ni], smem_u32(bbuf + boff));
                LDSM4T(bl[ni], smem_u32(bbuf + IB_SZ + boff));
            }
#pragma unroll
            for (int mi = 0; mi < 2; mi++)
#pragma unroll
                for (int ni = 0; ni < 4; ni++){
                    MMAF16(acc[mi][2*ni],   ah[mi], bh[ni][0], bh[ni][1]);
                    MMAF16(acc[mi][2*ni],   ah[mi], bl[ni][0], bl[ni][1]);
                    MMAF16(acc[mi][2*ni+1], ah[mi], bh[ni][2], bh[ni][3]);
                    MMAF16(acc[mi][2*ni+1], ah[mi], bl[ni][2], bl[ni][3]);
                }
        }
        __syncthreads();
    }
    // scalar stores: OUTF=513 is odd, rows only 4B-aligned
#pragma unroll
    for (int mi = 0; mi < 2; mi++){
        int r = wm*32 + mi*16 + (lane>>2);
#pragma unroll
        for (int nj = 0; nj < 8; nj++){
            int c = col0 + wn*64 + nj*8 + (lane&3)*2;
#pragma unroll
            for (int e = 0; e < 2; e++){
                int cc = c + e;
                if (cc < OUTF){
                    float bc = bout[cc];
                    size_t o0 = (size_t)(row0 + r)*OUTF + cc;
                    Out[o0]          = acc[mi][nj][e]     + bc;
                    Out[o0 + 8*OUTF] = acc[mi][nj][e + 2] + bc;
                }
            }
        }
    }
}

// ---- persistent HMMA recurrence (fp16 h, SINGLE fp16 U, 1 product) ----
#define OFF_HS   81920
#define HS_BUF   9216
#define OFF_EX   100352
#define RSMEM    (100352 + 8448)

__device__ __forceinline__ void grid_bar(unsigned target){
    __syncthreads();
    if (threadIdx.x == 0){
        asm volatile("red.release.gpu.add.u32 [%0], 1;" :: "l"(&g_bar) : "memory");
        unsigned v;
        do {
            asm volatile("ld.acquire.gpu.u32 %0, [%1];" : "=r"(v) : "l"(&g_bar) : "memory");
        } while (v < target);
    }
    __syncthreads();
}

__global__ __launch_bounds__(256,1) void k_recur_mma(){
    extern __shared__ char sm[];
    const int tid = threadIdx.x, lane = tid&31, w = tid>>5;
    const int blk = blockIdx.x;
    const int c0 = blk*32, u0 = blk*8;
    const int wm = w&3, wn = w>>2;
    char* UHI = sm;
    char* HSB = sm + OFF_HS;
    float* exch = (float*)(sm + OFF_EX);

    // resident U slice (single fp16), padded 80B rows (conflict-free ldmatrix.trans)
    for (int i = tid; i < 1024*4; i += 256){
        int k = i>>2, s = i&3;
        *(uint4*)(UHI + k*80 + s*16) =
            *(const uint4*)((const char*)(d_Uf16 + (size_t)k*NG + c0) + s*16);
    }

    float cst[2] = {0.f, 0.f};
    const int pb = tid>>2;
    const int pu = (tid&3)*2;
    const int hr = tid>>3, hsh = (tid&7)*16;
    const int hr2 = (tid+256)>>3, hsh2 = ((tid+256)&7)*16;

    for (int t = 0; t < Tt; t++){
        // prefetch G[t] early — latency hides under this step's GEMM
        const float* gp = &d_G[((size_t)t*Bb + pb)*NG + c0 + 4*pu];
        float4 g0 = __ldcg((const float4*)gp);
        float4 g1 = __ldcg((const float4*)(gp + 4));

        if (t > 0){
            const char* hsrc = (const char*)(d_Hall16 + ((size_t)(t-1)*Bb << 10));
            {
                uint4 v0 = __ldcg((const uint4*)(hsrc + hr*2048 + hsh));
                uint4 v1 = __ldcg((const uint4*)(hsrc + hr2*2048 + hsh2));
                *(uint4*)(HSB + hr*144 + hsh) = v0;
                *(uint4*)(HSB + hr2*144 + hsh2) = v1;
            }
            uint4 p1a = __ldcg((const uint4*)(hsrc + hr*2048 + 128 + hsh));
            uint4 p1b = __ldcg((const uint4*)(hsrc + hr2*2048 + 128 + hsh2));
            __syncthreads();

            float accP[2][4];
#pragma unroll
            for (int p=0;p<2;p++)
#pragma unroll
                for (int q=0;q<4;q++) accP[p][q]=0.f;

#pragma unroll 2
            for (int kc = 0; kc < 16; kc++){
                uint4 p2a, p2b;
                if (kc < 14){
                    p2a = __ldcg((const uint4*)(hsrc + hr*2048 + (kc+2)*128 + hsh));
                    p2b = __ldcg((const uint4*)(hsrc + hr2*2048 + (kc+2)*128 + hsh2));
                }
                char* hs = HSB + (kc&1)*HS_BUF;
#pragma unroll
                for (int ks = 0; ks < 4; ks++){
                    uint32_t ah[4], bh[4];
                    uint32_t aoff = (wm*16 + (lane&15))*144 + ks*32 + (lane>>4)*16;
                    LDSM4(ah, smem_u32(hs + aoff));
                    uint32_t brow = kc*64 + ks*16 + (lane&15);
                    uint32_t boff = brow*80 + wn*32 + (lane>>4)*16;
                    LDSM4T(bh, smem_u32(UHI + boff));
                    MMAF16(accP[0], ah, bh[0], bh[1]);
                    MMAF16(accP[1], ah, bh[2], bh[3]);
                }
                if (kc < 15){
                    char* nb = HSB + ((kc+1)&1)*HS_BUF;
                    *(uint4*)(nb + hr*144 + hsh) = p1a;
                    *(uint4*)(nb + hr2*144 + hsh2) = p1b;
                    __syncthreads();
                    p1a = p2a; p1b = p2b;
                }
            }
            {
                int r0 = wm*16 + (lane>>2);
                int cb = wn*16 + (lane&3)*2;
                exch[r0*33 + cb]       = accP[0][0];
                exch[r0*33 + cb + 1]   = accP[0][1];
                exch[(r0+8)*33 + cb]   = accP[0][2];
                exch[(r0+8)*33 + cb+1] = accP[0][3];
                exch[r0*33 + cb + 8]       = accP[1][0];
                exch[r0*33 + cb + 9]       = accP[1][1];
                exch[(r0+8)*33 + cb + 8]   = accP[1][2];
                exch[(r0+8)*33 + cb + 9]   = accP[1][3];
            }
            __syncthreads();
        }

#pragma unroll
        for (int j = 0; j < 2; j++){
            int u = pu + j;
            float4 g = (j == 0) ? g0 : g1;
            float zf = g.x, zi = g.y, zo = g.z, za = g.w;
            if (t > 0){
                zf += exch[pb*33 + 4*u];
                zi += exch[pb*33 + 4*u + 1];
                zo += exch[pb*33 + 4*u + 2];
                za += exch[pb*33 + 4*u + 3];
            }
            float f  = fsig(zf);
            float i2 = fsig(zi);
            float o  = fsig(zo);
            float cc = i2*tanhf(za) + f*cst[j];
            cst[j] = cc;
            float hv = o*tanhf(cc);
            d_Hall16[((size_t)t*Bb + pb)*Hh + u0 + u] = __float2half_rn(hv);
        }
        grid_bar((unsigned)(t + 1) * NBLK);
    }
}

// ---- launch ----
extern "C" void kernel_launch(void* const* d_in, const int* in_sizes, int n_in,
                              void* d_out, int out_size){
    (void)in_sizes; (void)n_in; (void)out_size;
    const float* x     = (const float*)d_in[0];
    const float* wfx_w = (const float*)d_in[1];
    const float* wfx_b = (const float*)d_in[2];
    const float* wix_w = (const float*)d_in[3];
    const float* wix_b = (const float*)d_in[4];
    const float* wox_w = (const float*)d_in[5];
    const float* wox_b = (const float*)d_in[6];
    const float* wcx_w = (const float*)d_in[7];
    const float* wcx_b = (const float*)d_in[8];
    const float* ufh_w = (const float*)d_in[9];
    const float* uih_w = (const float*)d_in[10];
    const float* uoh_w = (const float*)d_in[11];
    const float* uch_w = (const float*)d_in[12];
    const float* fco_w = (const float*)d_in[13];
    const float* fco_b = (const float*)d_in[14];
    float* out = (float*)d_out;

    cudaFuncSetAttribute(k_recur_mma, cudaFuncAttributeMaxDynamicSharedMemorySize, RSMEM);
    cudaFuncSetAttribute(k_gemm_in_mma, cudaFuncAttributeMaxDynamicSharedMemorySize, ISMEM);
    cudaFuncSetAttribute(k_gemm_out_mma, cudaFuncAttributeMaxDynamicSharedMemorySize, OSMEM);

    k_build_w16<<<(Ff*NG + 255)/256, 256>>>(wfx_w, wix_w, wox_w, wcx_w);
    k_split_x<<<(TBm*Ff + 255)/256, 256>>>(x);
    k_build_u<<<(Hh*NG + 255)/256, 256>>>(ufh_w, uih_w, uoh_w, uch_w);
    k_build_wout<<<(Hh*NOP + 255)/256, 256>>>(fco_w);
    k_build_misc<<<(NG + 255)/256, 256>>>(wfx_b, wix_b, wox_b, wcx_b);

    k_gemm_in_mma<<<dim3(NG/128, TBm/128), 256, ISMEM>>>();

    k_recur_mma<<<NBLK, 256, RSMEM>>>();

    k_gemm_out_mma<<<dim3(NOP/128, TBm/128), 256, OSMEM>>>(fco_b, out);
}

// round 16
// speedup vs baseline: 2.1047x; 1.3070x over previous
#include <cuda_runtime.h>
#include <cuda_bf16.h>
#include <cuda_fp16.h>
#include <cstdint>
#include <math.h>

#define Tt 128
#define Bb 64
#define Ff 512
#define Hh 1024
#define NG 4096
#define TBm 8192
#define OUTF 513
#define NOP 640
#define NBLK 128

static __device__ float d_Bcat[NG];
static __device__ float d_G[(size_t)TBm*NG];
static __device__ __half d_W16hi[(size_t)Ff*NG];
static __device__ __half d_W16lo[(size_t)Ff*NG];
static __device__ __half d_X16[(size_t)TBm*Ff];
static __device__ __half d_Uf16[(size_t)Hh*NG];
static __device__ __half d_Hall16[(size_t)TBm*Hh];
static __device__ __half d_Wo16hi[(size_t)Hh*NOP];
static __device__ __half d_Wo16lo[(size_t)Hh*NOP];
static __device__ uint32_t d_hfrag[2][64*4*32*4];   // [slot][kt][mt][lane][reg], 128KB each
static __device__ unsigned g_bar;

__constant__ int   c_CM[16] = {0,1,2,3, 1,0,3,2, 2,3,0,1, 3,2,1,0};
__constant__ float c_SG[16] = {1,1,1,1, -1,1,1,-1, -1,-1,1,1, -1,1,-1,1};

// ---- PTX helpers (sm_80-baseline, valid on sm_103) ----
__device__ __forceinline__ uint32_t smem_u32(const void* p){
    uint32_t a; asm("{ .reg .u64 t; cvta.to.shared.u64 t, %1; cvt.u32.u64 %0, t; }":"=r"(a):"l"(p)); return a;
}
#define LDSM4(r,a) asm volatile("ldmatrix.sync.aligned.m8n8.x4.shared.b16 {%0,%1,%2,%3}, [%4];" \
    :"=r"((r)[0]),"=r"((r)[1]),"=r"((r)[2]),"=r"((r)[3]):"r"(a))
#define LDSM4T(r,a) asm volatile("ldmatrix.sync.aligned.m8n8.x4.trans.shared.b16 {%0,%1,%2,%3}, [%4];" \
    :"=r"((r)[0]),"=r"((r)[1]),"=r"((r)[2]),"=r"((r)[3]):"r"(a))
#define MMAF16(c,a,b0,b1) asm volatile( \
    "mma.sync.aligned.m16n8k16.row.col.f32.f16.f16.f32 {%0,%1,%2,%3},{%4,%5,%6,%7},{%8,%9},{%0,%1,%2,%3};" \
    :"+f"((c)[0]),"+f"((c)[1]),"+f"((c)[2]),"+f"((c)[3]) \
    :"r"((a)[0]),"r"((a)[1]),"r"((a)[2]),"r"((a)[3]),"r"(b0),"r"(b1))
#define CPA16(dst,src) asm volatile("cp.async.cg.shared.global [%0], [%1], 16;"::"r"(dst),"l"(src))
#define CPA_COMMIT()   asm volatile("cp.async.commit_group;":::"memory")
#define CPA_WAIT1()    asm volatile("cp.async.wait_group 1;":::"memory")
#define CPA_WAIT0()    asm volatile("cp.async.wait_group 0;":::"memory")

__device__ __forceinline__ float fsig(float x){ return 1.f/(1.f + __expf(-x)); }

// ---- builds (gate-interleaved cols: col = 4h + g) ----
__global__ void k_build_w16(const float* __restrict__ wf, const float* __restrict__ wi,
                            const float* __restrict__ wo, const float* __restrict__ wc){
    int idx = blockIdx.x*blockDim.x + threadIdx.x;
    if (idx >= Ff*NG) return;
    int k = idx >> 12, c = idx & (NG-1);
    int g = c & 3, hh = c >> 2;
    int cb = hh>>8, bbp = hh&255, rb = k>>7, aa = k&127;
    const float* w = (g==0)?wf:(g==1)?wi:(g==2)?wo:wc;
    int m = rb*4+cb;
    float v = c_SG[m]*w[((size_t)c_CM[m]*128+aa)*256+bbp];
    __half hi = __float2half_rn(v);
    d_W16hi[idx] = hi;
    d_W16lo[idx] = __float2half_rn(v - __half2float(hi));
}
__global__ void k_split_x(const float* __restrict__ x){
    int idx = blockIdx.x*blockDim.x + threadIdx.x;
    if (idx >= TBm*Ff) return;
    d_X16[idx] = __float2half_rn(x[idx]);
}
__global__ void k_build_u(const float* __restrict__ uf, const float* __restrict__ ui,
                          const float* __restrict__ uo, const float* __restrict__ uc){
    int idx = blockIdx.x*blockDim.x + threadIdx.x;
    if (idx >= Hh*NG) return;
    int k = idx >> 12, c = idx & (NG-1);
    int g = c & 3, hh = c >> 2;
    int cb = hh>>8, bbp = hh&255, rb = k>>8, aa = k&255;
    const float* u = (g==0)?uf:(g==1)?ui:(g==2)?uo:uc;
    int m = rb*4+cb;
    float v = c_SG[m]*u[((size_t)c_CM[m]*256+aa)*256+bbp];
    d_Uf16[idx] = __float2half_rn(v);
}
__global__ void k_build_wout(const float* __restrict__ Wo){
    int idx = blockIdx.x*blockDim.x + threadIdx.x;
    if (idx >= Hh*NOP) return;
    int k = idx / NOP, n = idx % NOP;
    float v = (n < OUTF) ? Wo[(size_t)k*OUTF + n] : 0.f;
    __half hi = __float2half_rn(v);
    d_Wo16hi[idx] = hi;
    d_Wo16lo[idx] = __float2half_rn(v - __half2float(hi));
}
__global__ void k_build_misc(const float* __restrict__ bf, const float* __restrict__ bi,
                             const float* __restrict__ bo, const float* __restrict__ bc){
    int idx = blockIdx.x*blockDim.x + threadIdx.x;
    if (idx == 0) g_bar = 0u;
    if (idx < NG){
        int g = idx & 3, hh = idx >> 2;
        const float* b = (g==0)?bf:(g==1)?bi:(g==2)?bo:bc;
        d_Bcat[idx] = b[hh];
    }
}

// ---- shared tile constants ----
#define IA_STR 144
#define IB_STR 272
#define IA_SZ  (128*IA_STR)
#define IB_SZ  (64*IB_STR)

// ---- HMMA input GEMM (fp16: A=X16 single, B=W16 hi/lo, 2 products); 2 blk/SM ----
#define GIBUF  (IA_SZ + 2*IB_SZ)
#define ISMEM  GIBUF

__device__ __forceinline__ void gi_load(char* buf, int row0, int col0, int kc, int tid){
#pragma unroll
    for (int j = 0; j < 4; j++){
        int i = tid + j*256;
        int r = i >> 3, s = i & 7;
        const char* src = (const char*)(d_X16 + (size_t)(row0 + r)*Ff + kc*64 + s*8);
        CPA16(smem_u32(buf + r*IA_STR + s*16), src);
    }
    char* bbuf = buf + IA_SZ;
    const __half* Bc[2] = {d_W16hi, d_W16lo};
#pragma unroll
    for (int j = 0; j < 8; j++){
        int i = tid + j*256;
        int comp = i >> 10, rem = i & 1023, r = rem >> 4, s = rem & 15;
        const char* src = (const char*)(Bc[comp] + (size_t)(kc*64 + r)*NG + col0 + s*8);
        CPA16(smem_u32(bbuf + comp*IB_SZ + r*IB_STR + s*16), src);
    }
    CPA_COMMIT();
}

__global__ __launch_bounds__(256,2) void k_gemm_in_mma(){
    extern __shared__ char sm[];
    const int tid = threadIdx.x, lane = tid&31, w = tid>>5;
    const int wm = w&3, wn = w>>2;
    const int col0 = blockIdx.x*128, row0 = blockIdx.y*128;
    float acc[2][8][4];
#pragma unroll
    for (int mi=0;mi<2;mi++)
#pragma unroll
        for (int nj=0;nj<8;nj++)
#pragma unroll
            for (int q=0;q<4;q++) acc[mi][nj][q]=0.f;

    for (int kc = 0; kc < 8; kc++){
        gi_load(sm, row0, col0, kc, tid);
        CPA_WAIT0();
        __syncthreads();
        char* abuf = sm;
        char* bbuf = sm + IA_SZ;
#pragma unroll
        for (int ks = 0; ks < 4; ks++){
            uint32_t ah[2][4], bh[4][4], bl[4][4];
#pragma unroll
            for (int mi = 0; mi < 2; mi++){
                uint32_t aoff = (wm*32 + mi*16 + (lane&15))*IA_STR + ks*32 + (lane>>4)*16;
                LDSM4(ah[mi], smem_u32(abuf + aoff));
            }
#pragma unroll
            for (int ni = 0; ni < 4; ni++){
                uint32_t boff = (ks*16 + (lane&15))*IB_STR + wn*128 + ni*32 + (lane>>4)*16;
                LDSM4T(bh[ni], smem_u32(bbuf + boff));
                LDSM4T(bl[ni], smem_u32(bbuf + IB_SZ + boff));
            }
#pragma unroll
            for (int mi = 0; mi < 2; mi++)
#pragma unroll
                for (int ni = 0; ni < 4; ni++){
                    MMAF16(acc[mi][2*ni],   ah[mi], bh[ni][0], bh[ni][1]);
                    MMAF16(acc[mi][2*ni],   ah[mi], bl[ni][0], bl[ni][1]);
                    MMAF16(acc[mi][2*ni+1], ah[mi], bh[ni][2], bh[ni][3]);
                    MMAF16(acc[mi][2*ni+1], ah[mi], bl[ni][2], bl[ni][3]);
                }
        }
        __syncthreads();
    }
#pragma unroll
    for (int mi = 0; mi < 2; mi++){
        int r = wm*32 + mi*16 + (lane>>2);
#pragma unroll
        for (int nj = 0; nj < 8; nj++){
            int c = col0 + wn*64 + nj*8 + (lane&3)*2;
            float2 bc = *(const float2*)&d_Bcat[c];
            size_t g0 = (size_t)(row0 + r)*NG + c;
            *(float2*)&d_G[g0] = make_float2(acc[mi][nj][0] + bc.x, acc[mi][nj][1] + bc.y);
            *(float2*)&d_G[g0 + 8*NG] = make_float2(acc[mi][nj][2] + bc.x, acc[mi][nj][3] + bc.y);
        }
    }
}

// ---- HMMA output GEMM (fp16: A = Hall16 single, B = Wo16 hi/lo) ----
#define OA_SZ  (128*IA_STR)
#define OBUF   (OA_SZ + 2*IB_SZ)
#define OSMEM  (2*OBUF)

__device__ __forceinline__ void go_load(char* buf, int row0, int col0, int kc, int tid){
#pragma unroll
    for (int j = 0; j < 4; j++){
        int i = tid + j*256;
        int r = i >> 3, s = i & 7;
        const char* src = (const char*)(d_Hall16 + (size_t)(row0 + r)*Hh + kc*64 + s*8);
        CPA16(smem_u32(buf + r*IA_STR + s*16), src);
    }
    char* bbuf = buf + OA_SZ;
    const __half* Bc[2] = {d_Wo16hi, d_Wo16lo};
#pragma unroll
    for (int j = 0; j < 8; j++){
        int i = tid + j*256;
        int comp = i >> 10, rem = i & 1023, r = rem >> 4, s = rem & 15;
        const char* src = (const char*)(Bc[comp] + (size_t)(kc*64 + r)*NOP + col0 + s*8);
        CPA16(smem_u32(bbuf + comp*IB_SZ + r*IB_STR + s*16), src);
    }
    CPA_COMMIT();
}

__global__ __launch_bounds__(256,2) void k_gemm_out_mma(const float* __restrict__ bout,
                                                        float* __restrict__ Out){
    extern __shared__ char sm[];
    const int tid = threadIdx.x, lane = tid&31, w = tid>>5;
    const int wm = w&3, wn = w>>2;
    const int col0 = blockIdx.x*128, row0 = blockIdx.y*128;
    float acc[2][8][4];
#pragma unroll
    for (int mi=0;mi<2;mi++)
#pragma unroll
        for (int nj=0;nj<8;nj++)
#pragma unroll
            for (int q=0;q<4;q++) acc[mi][nj][q]=0.f;

    go_load(sm, row0, col0, 0, tid);
    for (int kc = 0; kc < 16; kc++){
        if (kc < 15) go_load(sm + ((kc+1)&1)*OBUF, row0, col0, kc+1, tid);
        if (kc < 15) CPA_WAIT1(); else CPA_WAIT0();
        __syncthreads();
        char* abuf = sm + (kc&1)*OBUF;
        char* bbuf = abuf + OA_SZ;
#pragma unroll
        for (int ks = 0; ks < 4; ks++){
            uint32_t ah[2][4], bh[4][4], bl[4][4];
#pragma unroll
            for (int mi = 0; mi < 2; mi++){
                uint32_t aoff = (wm*32 + mi*16 + (lane&15))*IA_STR + ks*32 + (lane>>4)*16;
                LDSM4(ah[mi], smem_u32(abuf + aoff));
            }
#pragma unroll
            for (int ni = 0; ni < 4; ni++){
                uint32_t boff = (ks*16 + (lane&15))*IB_STR + wn*128 + ni*32 + (lane>>4)*16;
                LDSM4T(bh[ni], smem_u32(bbuf + boff));
                LDSM4T(bl[ni], smem_u32(bbuf + IB_SZ + boff));
            }
#pragma unroll
            for (int mi = 0; mi < 2; mi++)
#pragma unroll
                for (int ni = 0; ni < 4; ni++){
                    MMAF16(acc[mi][2*ni],   ah[mi], bh[ni][0], bh[ni][1]);
                    MMAF16(acc[mi][2*ni],   ah[mi], bl[ni][0], bl[ni][1]);
                    MMAF16(acc[mi][2*ni+1], ah[mi], bh[ni][2], bh[ni][3]);
                    MMAF16(acc[mi][2*ni+1], ah[mi], bl[ni][2], bl[ni][3]);
                }
        }
        __syncthreads();
    }
    // scalar stores: OUTF=513 is odd, rows only 4B-aligned
#pragma unroll
    for (int mi = 0; mi < 2; mi++){
        int r = wm*32 + mi*16 + (lane>>2);
#pragma unroll
        for (int nj = 0; nj < 8; nj++){
            int c = col0 + wn*64 + nj*8 + (lane&3)*2;
#pragma unroll
            for (int e = 0; e < 2; e++){
                int cc = c + e;
                if (cc < OUTF){
                    float bc = bout[cc];
                    size_t o0 = (size_t)(row0 + r)*OUTF + cc;
                    Out[o0]          = acc[mi][nj][e]     + bc;
                    Out[o0 + 8*OUTF] = acc[mi][nj][e + 2] + bc;
                }
            }
        }
    }
}

// ---- persistent HMMA recurrence: fragment-direct A, resident fp16 U, no staging ----
#define OFF_EX   81920
#define RSMEM    (81920 + 8448)

__device__ __forceinline__ void grid_bar(unsigned target){
    __syncthreads();
    if (threadIdx.x == 0){
        asm volatile("red.release.gpu.add.u32 [%0], 1;" :: "l"(&g_bar) : "memory");
        unsigned v;
        do {
            asm volatile("ld.acquire.gpu.u32 %0, [%1];" : "=r"(v) : "l"(&g_bar) : "memory");
        } while (v < target);
    }
    __syncthreads();
}

__global__ __launch_bounds__(256,1) void k_recur_mma(){
    extern __shared__ char sm[];
    const int tid = threadIdx.x, lane = tid&31, w = tid>>5;
    const int blk = blockIdx.x;
    const int c0 = blk*32, u0 = blk*8;
    const int wm = w&3, wn = w>>2;
    char* UHI = sm;
    float* exch = (float*)(sm + OFF_EX);

    // resident U slice (single fp16), padded 80B rows (conflict-free ldmatrix.trans)
    for (int i = tid; i < 1024*4; i += 256){
        int k = i>>2, s = i&3;
        *(uint4*)(UHI + k*80 + s*16) =
            *(const uint4*)((const char*)(d_Uf16 + (size_t)k*NG + c0) + s*16);
    }

    float cst[2] = {0.f, 0.f};
    const int pb = tid>>2;
    const int pu = (tid&3)*2;
    // writer fragment index: [kt=blk>>1][mt=tid>>6][lane=((tid>>2)&7)*4+(tid&3)][reg]
    const int wlane = ((tid>>2)&7)*4 + (tid&3);
    const int wmt   = tid>>6;
    const int wreg  = ((tid>>5)&1) + 2*(blk&1);
    const uint32_t widx = (uint32_t)((((blk>>1)*4 + wmt)*32 + wlane)*4 + wreg);

    for (int t = 0; t < Tt; t++){
        // prefetch G[t] early — latency hides under this step's GEMM
        const float* gp = &d_G[((size_t)t*Bb + pb)*NG + c0 + 4*pu];
        float4 g0 = __ldcg((const float4*)gp);
        float4 g1 = __ldcg((const float4*)(gp + 4));

        if (t > 0){
            const uint4* fb = (const uint4*)d_hfrag[(t-1)&1];
            float accP[2][4];
#pragma unroll
            for (int p=0;p<2;p++)
#pragma unroll
                for (int q=0;q<4;q++) accP[p][q]=0.f;

            uint4 af[8];
#pragma unroll
            for (int p = 0; p < 8; p++)
                af[p] = __ldcg(fb + (p*4 + wm)*32 + lane);

#pragma unroll 8
            for (int kt = 0; kt < 64; kt++){
                uint4 a = af[kt & 7];
                if (kt < 56)
                    af[kt & 7] = __ldcg(fb + ((kt+8)*4 + wm)*32 + lane);
                uint32_t ah[4] = {a.x, a.y, a.z, a.w};
                uint32_t bh[4];
                uint32_t brow = kt*16 + (lane&15);
                uint32_t boff = brow*80 + wn*32 + (lane>>4)*16;
                LDSM4T(bh, smem_u32(UHI + boff));
                MMAF16(accP[0], ah, bh[0], bh[1]);
                MMAF16(accP[1], ah, bh[2], bh[3]);
            }
            {
                int r0 = wm*16 + (lane>>2);
                int cb = wn*16 + (lane&3)*2;
                exch[r0*33 + cb]       = accP[0][0];
                exch[r0*33 + cb + 1]   = accP[0][1];
                exch[(r0+8)*33 + cb]   = accP[0][2];
                exch[(r0+8)*33 + cb+1] = accP[0][3];
                exch[r0*33 + cb + 8]       = accP[1][0];
                exch[r0*33 + cb + 9]       = accP[1][1];
                exch[(r0+8)*33 + cb + 8]   = accP[1][2];
                exch[(r0+8)*33 + cb + 9]   = accP[1][3];
            }
            __syncthreads();
        }

        float hv[2];
#pragma unroll
        for (int j = 0; j < 2; j++){
            int u = pu + j;
            float4 g = (j == 0) ? g0 : g1;
            float zf = g.x, zi = g.y, zo = g.z, za = g.w;
            if (t > 0){
                zf += exch[pb*33 + 4*u];
                zi += exch[pb*33 + 4*u + 1];
                zo += exch[pb*33 + 4*u + 2];
                za += exch[pb*33 + 4*u + 3];
            }
            float f  = fsig(zf);
            float i2 = fsig(zi);
            float o  = fsig(zo);
            float cc = i2*tanhf(za) + f*cst[j];
            cst[j] = cc;
            hv[j] = o*tanhf(cc);
        }
        // pack two halves -> one 4B store each to fragment buffer + row-major Hall16
        {
            __half2 hp = __floats2half2_rn(hv[0], hv[1]);
            uint32_t hbits = *(uint32_t*)&hp;
            d_hfrag[t&1][widx] = hbits;
            *(uint32_t*)&d_Hall16[((size_t)t*Bb + pb)*Hh + u0 + pu] = hbits;
        }
        grid_bar((unsigned)(t + 1) * NBLK);
    }
}

// ---- launch ----
extern "C" void kernel_launch(void* const* d_in, const int* in_sizes, int n_in,
                              void* d_out, int out_size){
    (void)in_sizes; (void)n_in; (void)out_size;
    const float* x     = (const float*)d_in[0];
    const float* wfx_w = (const float*)d_in[1];
    const float* wfx_b = (const float*)d_in[2];
    const float* wix_w = (const float*)d_in[3];
    const float* wix_b = (const float*)d_in[4];
    const float* wox_w = (const float*)d_in[5];
    const float* wox_b = (const float*)d_in[6];
    const float* wcx_w = (const float*)d_in[7];
    const float* wcx_b = (const float*)d_in[8];
    const float* ufh_w = (const float*)d_in[9];
    const float* uih_w = (const float*)d_in[10];
    const float* uoh_w = (const float*)d_in[11];
    const float* uch_w = (const float*)d_in[12];
    const float* fco_w = (const float*)d_in[13];
    const float* fco_b = (const float*)d_in[14];
    float* out = (float*)d_out;

    cudaFuncSetAttribute(k_recur_mma, cudaFuncAttributeMaxDynamicSharedMemorySize, RSMEM);
    cudaFuncSetAttribute(k_gemm_in_mma, cudaFuncAttributeMaxDynamicSharedMemorySize, ISMEM);
    cudaFuncSetAttribute(k_gemm_out_mma, cudaFuncAttributeMaxDynamicSharedMemorySize, OSMEM);

    k_build_w16<<<(Ff*NG + 255)/256, 256>>>(wfx_w, wix_w, wox_w, wcx_w);
    k_split_x<<<(TBm*Ff + 255)/256, 256>>>(x);
    k_build_u<<<(Hh*NG + 255)/256, 256>>>(ufh_w, uih_w, uoh_w, uch_w);
    k_build_wout<<<(Hh*NOP + 255)/256, 256>>>(fco_w);
    k_build_misc<<<(NG + 255)/256, 256>>>(wfx_b, wix_b, wox_b, wcx_b);

    k_gemm_in_mma<<<dim3(NG/128, TBm/128), 256, ISMEM>>>();

    k_recur_mma<<<NBLK, 256, RSMEM>>>();

    k_gemm_out_mma<<<dim3(NOP/128, TBm/128), 256, OSMEM>>>(fco_b, out);
}